// round 6
// baseline (speedup 1.0000x reference)
#include <cuda_runtime.h>
#include <cuda_bf16.h>
#include <mma.h>
#include <stdint.h>
#include <math.h>

using namespace nvcuda;

// Problem constants (AttentionLayer_11776800325798)
#define NMAX   50000
#define EMAX   500000
#define TT     3
#define RR     5
#define HH     8
#define DKK    16
#define FDIM   128
#define NRH    (NMAX * RR * HH)                      // 2,000,000
#define NL_CAP (((NMAX / 128) + TT + 1) * 128)       // 50432, 128-padded per type
#define SQRT_DK 4.0f
#define MATPAD 272                                   // SMEM matrix stride (floats)
#define LDA 136                                      // bf16 elems per row (128 + 8 pad)
#define LDB 136
#define FLD 132                                      // fp32 staging tile stride

// ---------------- scratch (static __device__, no allocation) ----------------
__device__ float    g_k[NMAX * FDIM];
__device__ float    g_q[NMAX * FDIM];
__device__ float    g_v[NMAX * FDIM];
__device__ float    g_acc[NMAX * FDIM];
__device__ float    g_a[EMAX * HH];
__device__ float    g_den[NRH];
__device__ int      g_nlist[NL_CAP];
__device__ int      g_cnt[TT];
__device__ int      g_cur[TT];
__device__ int      g_poff[TT + 1];
// edges sorted by etype
__device__ int      g_esrc[EMAX];
__device__ int      g_edst[EMAX];
__device__ int      g_eet[EMAX];
__device__ int      g_ecnt[RR];
__device__ int      g_ecur[RR];
__device__ int      g_eoff[RR + 1];

// fp32 -> bf16 hi + bf16 lo (packed pairs)
__device__ __forceinline__ uint32_t bfsplit(float a, float b, uint32_t& lo) {
    __nv_bfloat162 h = __floats2bfloat162_rn(a, b);
    float ra = a - __bfloat162float(h.x);
    float rb = b - __bfloat162float(h.y);
    __nv_bfloat162 l = __floats2bfloat162_rn(ra, rb);
    lo = *reinterpret_cast<uint32_t*>(&l);
    return *reinterpret_cast<uint32_t*>(&h);
}

// ============================================================================
// K0: zero scratch
// ============================================================================
__global__ void zero_kernel() {
    int stride = gridDim.x * blockDim.x;
    for (int idx = blockIdx.x * blockDim.x + threadIdx.x; idx < NMAX * FDIM; idx += stride) {
        g_acc[idx] = 0.f;
        if (idx < NRH) g_den[idx] = 0.f;
        if (idx < NL_CAP) g_nlist[idx] = -1;
        if (idx < TT) { g_cnt[idx] = 0; g_cur[idx] = 0; }
        if (idx < RR) { g_ecnt[idx] = 0; g_ecur[idx] = 0; }
    }
}

// ---------------- counting sort of nodes by type (warp-aggregated atomics) ----------------
__global__ void hist_kernel(const int* __restrict__ ntype, int N) {
    int i = blockIdx.x * blockDim.x + threadIdx.x;
    int t = (i < N) ? ntype[i] : -1;
    #pragma unroll
    for (int tt = 0; tt < TT; tt++) {
        unsigned mask = __ballot_sync(0xFFFFFFFFu, t == tt);
        if (t == tt) {
            int lane = threadIdx.x & 31;
            if (lane == __ffs(mask) - 1) atomicAdd(&g_cnt[tt], __popc(mask));
        }
    }
}
__global__ void scan_kernel() {
    if (threadIdx.x == 0 && blockIdx.x == 0) {
        int o = 0;
        for (int t = 0; t < TT; t++) { g_poff[t] = o; o += ((g_cnt[t] + 127) / 128) * 128; }
        g_poff[TT] = o;
        int eo = 0;
        for (int r = 0; r < RR; r++) { g_eoff[r] = eo; eo += g_ecnt[r]; }
        g_eoff[RR] = eo;
    }
}
__global__ void scatter_kernel(const int* __restrict__ ntype, int N) {
    int i = blockIdx.x * blockDim.x + threadIdx.x;
    int t = (i < N) ? ntype[i] : -1;
    #pragma unroll
    for (int tt = 0; tt < TT; tt++) {
        unsigned mask = __ballot_sync(0xFFFFFFFFu, t == tt);
        if (t == tt) {
            int lane = threadIdx.x & 31;
            int leader = __ffs(mask) - 1;
            int rank = __popc(mask & ((1u << lane) - 1));
            int base = 0;
            if (lane == leader) base = atomicAdd(&g_cur[tt], __popc(mask));
            base = __shfl_sync(mask, base, leader);
            g_nlist[g_poff[tt] + base + rank] = i;
        }
    }
}

// ---------------- counting sort of edges by etype ----------------
__global__ void ehist_kernel(const int* __restrict__ etype, int E) {
    int i = blockIdx.x * blockDim.x + threadIdx.x;
    int r = (i < E) ? etype[i] : -1;
    #pragma unroll
    for (int rr = 0; rr < RR; rr++) {
        unsigned mask = __ballot_sync(0xFFFFFFFFu, r == rr);
        if (r == rr) {
            int lane = threadIdx.x & 31;
            if (lane == __ffs(mask) - 1) atomicAdd(&g_ecnt[rr], __popc(mask));
        }
    }
}
__global__ void escatter_kernel(const int* __restrict__ src, const int* __restrict__ dst,
                                const int* __restrict__ etype, int E) {
    int i = blockIdx.x * blockDim.x + threadIdx.x;
    int r = (i < E) ? etype[i] : -1;
    #pragma unroll
    for (int rr = 0; rr < RR; rr++) {
        unsigned mask = __ballot_sync(0xFFFFFFFFu, r == rr);
        if (r == rr) {
            int lane = threadIdx.x & 31;
            int leader = __ffs(mask) - 1;
            int rank = __popc(mask & ((1u << lane) - 1));
            int base = 0;
            if (lane == leader) base = atomicAdd(&g_ecur[rr], __popc(mask));
            base = __shfl_sync(mask, base, leader);
            int pos = g_eoff[rr] + base + rank;
            g_esrc[pos] = src[i];
            g_edst[pos] = dst[i];
            g_eet[pos]  = rr;
        }
    }
}

// ============================================================================
// K1: typed projections via wmma bf16 split (fp32-accurate)
// ============================================================================
__global__ __launch_bounds__(256) void proj_wmma_kernel(
    const float* __restrict__ x, const int* __restrict__ ntype,
    const float* __restrict__ Wk, const float* __restrict__ bk,
    const float* __restrict__ Wq, const float* __restrict__ bq,
    const float* __restrict__ Wv, const float* __restrict__ bv)
{
    extern __shared__ __align__(16) char dynsm[];
    __nv_bfloat16* Ah = (__nv_bfloat16*)dynsm;
    __nv_bfloat16* Al = Ah + 128 * LDA;
    __nv_bfloat16* Bh = Al + 128 * LDA;
    __nv_bfloat16* Bl = Bh + 128 * LDB;
    __shared__ int s_nl[128];
    __shared__ int s_t;
    __shared__ __align__(16) float stg[8][16][24];

    int tid = threadIdx.x, w = tid >> 5, lane = tid & 31;
    if (tid < 128) s_nl[tid] = g_nlist[blockIdx.x * 128 + tid];
    __syncthreads();
    if (tid == 0) {
        int t = -1;
        for (int m = 0; m < 128; m++) if (s_nl[m] >= 0) { t = ntype[s_nl[m]]; break; }
        s_t = t;
    }
    __syncthreads();
    if (s_t < 0) return;

    // stage A: gather x rows, split into bf16 hi/lo
    for (int idx = tid; idx < 128 * 32; idx += 256) {
        int m = idx >> 5, c = (idx & 31) * 4;
        int n = s_nl[m];
        float4 f = (n >= 0) ? *(const float4*)(x + (size_t)n * FDIM + c)
                            : make_float4(0.f, 0.f, 0.f, 0.f);
        uint32_t l0, l1;
        uint32_t h0 = bfsplit(f.x, f.y, l0), h1 = bfsplit(f.z, f.w, l1);
        *(uint32_t*)(Ah + m * LDA + c)     = h0;
        *(uint32_t*)(Ah + m * LDA + c + 2) = h1;
        *(uint32_t*)(Al + m * LDA + c)     = l0;
        *(uint32_t*)(Al + m * LDA + c + 2) = l1;
    }

    int row_m = w * 16;
    int r = lane >> 1, c0 = (lane & 1) * 8;
    int gr = s_nl[row_m + r];

    for (int set = 0; set < 3; set++) {
        const float* W    = ((set == 0) ? Wk : (set == 1) ? Wq : Wv) + s_t * FDIM * FDIM;
        const float* bias = ((set == 0) ? bk : (set == 1) ? bq : bv) + s_t * FDIM;
        for (int idx = tid; idx < 128 * 32; idx += 256) {
            int kk = idx >> 5, c = (idx & 31) * 4;
            float4 f = *(const float4*)(W + kk * FDIM + c);
            uint32_t l0, l1;
            uint32_t h0 = bfsplit(f.x, f.y, l0), h1 = bfsplit(f.z, f.w, l1);
            *(uint32_t*)(Bh + kk * LDB + c)     = h0;
            *(uint32_t*)(Bh + kk * LDB + c + 2) = h1;
            *(uint32_t*)(Bl + kk * LDB + c)     = l0;
            *(uint32_t*)(Bl + kk * LDB + c + 2) = l1;
        }
        __syncthreads();

        wmma::fragment<wmma::accumulator, 16, 16, 16, float> acc[8];
        #pragma unroll
        for (int ni = 0; ni < 8; ni++) wmma::fill_fragment(acc[ni], 0.f);
        for (int k = 0; k < 8; k++) {
            wmma::fragment<wmma::matrix_a, 16, 16, 16, __nv_bfloat16, wmma::row_major> ah, al;
            wmma::load_matrix_sync(ah, Ah + row_m * LDA + k * 16, LDA);
            wmma::load_matrix_sync(al, Al + row_m * LDA + k * 16, LDA);
            #pragma unroll
            for (int ni = 0; ni < 8; ni++) {
                wmma::fragment<wmma::matrix_b, 16, 16, 16, __nv_bfloat16, wmma::row_major> bh, bl;
                wmma::load_matrix_sync(bh, Bh + (k * 16) * LDB + ni * 16, LDB);
                wmma::load_matrix_sync(bl, Bl + (k * 16) * LDB + ni * 16, LDB);
                wmma::mma_sync(acc[ni], ah, bh, acc[ni]);
                wmma::mma_sync(acc[ni], ah, bl, acc[ni]);
                wmma::mma_sync(acc[ni], al, bh, acc[ni]);
            }
        }

        float* ob = (set == 0) ? g_k : (set == 1) ? g_q : g_v;
        for (int ni = 0; ni < 8; ni++) {
            wmma::store_matrix_sync(&stg[w][0][0], acc[ni], 24, wmma::mem_row_major);
            __syncwarp();
            if (gr >= 0) {
                int col = ni * 16 + c0;
                float4 v0 = *(float4*)&stg[w][r][c0];
                float4 v1 = *(float4*)&stg[w][r][c0 + 4];
                v0.x += bias[col + 0]; v0.y += bias[col + 1];
                v0.z += bias[col + 2]; v0.w += bias[col + 3];
                v1.x += bias[col + 4]; v1.y += bias[col + 5];
                v1.z += bias[col + 6]; v1.w += bias[col + 7];
                *(float4*)(ob + (size_t)gr * FDIM + col)     = v0;
                *(float4*)(ob + (size_t)gr * FDIM + col + 4) = v1;
            }
            __syncwarp();
        }
        __syncthreads();
    }
}

// ============================================================================
// K2: edge scores + exp + segment denom. Edges sorted by etype; each warp owns
// a contiguous chunk so the lane's 16x4 matrix strip stays cached in registers.
// ============================================================================
__global__ __launch_bounds__(256, 2) void score_kernel(
    const float* __restrict__ rel_pri, const float* __restrict__ rel_att, int E) {
    __shared__ __align__(16) float s_att[RR * HH * MATPAD];
    __shared__ float s_pri[RR * HH];
    for (int idx = threadIdx.x; idx < RR * HH * DKK * DKK; idx += 256) {
        int mat = idx >> 8, inner = idx & 255;
        s_att[mat * MATPAD + inner] = rel_att[idx];
    }
    if (threadIdx.x < RR * HH) s_pri[threadIdx.x] = rel_pri[threadIdx.x];
    __syncthreads();

    int lane = threadIdx.x & 31;
    int h = lane >> 2, qq = lane & 3;
    int gw = blockIdx.x * 8 + (threadIdx.x >> 5);
    int nw = gridDim.x * 8;
    int chunk = (E + nw - 1) / nw;
    int e0 = gw * chunk;
    int e1 = min(e0 + chunk, E);

    float4 strip[16];
    float pri = 0.f;
    int cr = -1;
    for (int e = e0; e < e1; e++) {
        int s = g_esrc[e], d = g_edst[e], r = g_eet[e];
        if (r != cr) {
            cr = r;
            const float* A = s_att + (r * HH + h) * MATPAD + qq * 4;
            #pragma unroll
            for (int dd = 0; dd < 16; dd++) strip[dd] = *(const float4*)(A + dd * DKK);
            pri = s_pri[r * HH + h] * (1.0f / SQRT_DK);
        }
        const float4* kp = (const float4*)(g_k + s * FDIM + h * DKK);
        float4 qv = *(const float4*)(g_q + d * FDIM + h * DKK + qq * 4);
        float4 t = make_float4(0.f, 0.f, 0.f, 0.f);
        #pragma unroll
        for (int i = 0; i < 4; i++) {
            float4 kv = kp[i];
            t.x = fmaf(kv.x, strip[i*4+0].x, t.x); t.y = fmaf(kv.x, strip[i*4+0].y, t.y);
            t.z = fmaf(kv.x, strip[i*4+0].z, t.z); t.w = fmaf(kv.x, strip[i*4+0].w, t.w);
            t.x = fmaf(kv.y, strip[i*4+1].x, t.x); t.y = fmaf(kv.y, strip[i*4+1].y, t.y);
            t.z = fmaf(kv.y, strip[i*4+1].z, t.z); t.w = fmaf(kv.y, strip[i*4+1].w, t.w);
            t.x = fmaf(kv.z, strip[i*4+2].x, t.x); t.y = fmaf(kv.z, strip[i*4+2].y, t.y);
            t.z = fmaf(kv.z, strip[i*4+2].z, t.z); t.w = fmaf(kv.z, strip[i*4+2].w, t.w);
            t.x = fmaf(kv.w, strip[i*4+3].x, t.x); t.y = fmaf(kv.w, strip[i*4+3].y, t.y);
            t.z = fmaf(kv.w, strip[i*4+3].z, t.z); t.w = fmaf(kv.w, strip[i*4+3].w, t.w);
        }
        float sc = t.x*qv.x + t.y*qv.y + t.z*qv.z + t.w*qv.w;
        sc += __shfl_xor_sync(0xFFFFFFFFu, sc, 1);
        sc += __shfl_xor_sync(0xFFFFFFFFu, sc, 2);
        sc *= pri;
        if (qq == 0) {
            float p = __expf(sc);
            g_a[e * HH + h] = p;
            atomicAdd(&g_den[(d * RR + r) * HH + h], p);
        }
    }
}

// ============================================================================
// K4: weighted message aggregation (same chunked + register-strip scheme)
// ============================================================================
__global__ __launch_bounds__(256, 2) void agg_kernel(
    const float* __restrict__ rel_msg, int E) {
    __shared__ __align__(16) float s_msg[RR * HH * MATPAD];
    for (int idx = threadIdx.x; idx < RR * HH * DKK * DKK; idx += 256) {
        int mat = idx >> 8, inner = idx & 255;
        s_msg[mat * MATPAD + inner] = rel_msg[idx];
    }
    __syncthreads();

    int lane = threadIdx.x & 31;
    int h = lane >> 2, qq = lane & 3;
    int gw = blockIdx.x * 8 + (threadIdx.x >> 5);
    int nw = gridDim.x * 8;
    int chunk = (E + nw - 1) / nw;
    int e0 = gw * chunk;
    int e1 = min(e0 + chunk, E);

    float4 strip[16];
    int cr = -1;
    for (int e = e0; e < e1; e++) {
        int s = g_esrc[e], d = g_edst[e], r = g_eet[e];
        if (r != cr) {
            cr = r;
            const float* M = s_msg + (r * HH + h) * MATPAD + qq * 4;
            #pragma unroll
            for (int dd = 0; dd < 16; dd++) strip[dd] = *(const float4*)(M + dd * DKK);
        }
        float p = g_a[e * HH + h];
        float den = g_den[(d * RR + r) * HH + h];
        float attw = p / den;
        const float4* vp = (const float4*)(g_v + s * FDIM + h * DKK);
        float4 o = make_float4(0.f, 0.f, 0.f, 0.f);
        #pragma unroll
        for (int i = 0; i < 4; i++) {
            float4 vv = vp[i];
            o.x = fmaf(vv.x, strip[i*4+0].x, o.x); o.y = fmaf(vv.x, strip[i*4+0].y, o.y);
            o.z = fmaf(vv.x, strip[i*4+0].z, o.z); o.w = fmaf(vv.x, strip[i*4+0].w, o.w);
            o.x = fmaf(vv.y, strip[i*4+1].x, o.x); o.y = fmaf(vv.y, strip[i*4+1].y, o.y);
            o.z = fmaf(vv.y, strip[i*4+1].z, o.z); o.w = fmaf(vv.y, strip[i*4+1].w, o.w);
            o.x = fmaf(vv.z, strip[i*4+2].x, o.x); o.y = fmaf(vv.z, strip[i*4+2].y, o.y);
            o.z = fmaf(vv.z, strip[i*4+2].z, o.z); o.w = fmaf(vv.z, strip[i*4+2].w, o.w);
            o.x = fmaf(vv.w, strip[i*4+3].x, o.x); o.y = fmaf(vv.w, strip[i*4+3].y, o.y);
            o.z = fmaf(vv.w, strip[i*4+3].z, o.z); o.w = fmaf(vv.w, strip[i*4+3].w, o.w);
        }
        float4 add = make_float4(attw*o.x, attw*o.y, attw*o.z, attw*o.w);
        atomicAdd((float4*)(g_acc + d * FDIM + h * DKK + qq * 4), add);
    }
}

// ============================================================================
// K5: mean-over-etypes, Wa proj (wmma split-bf16), skip blend, per-type LN
// One block = 128 nodes, 256 threads. dyn SMEM: Ah|Al|Bh|Bl; fp32 tile aliases it.
// ============================================================================
__global__ __launch_bounds__(256) void final_wmma_kernel(
    const float* __restrict__ x, const int* __restrict__ ntype,
    const float* __restrict__ Wa, const float* __restrict__ ba,
    const float* __restrict__ skipv,
    const float* __restrict__ ln_g, const float* __restrict__ ln_b,
    float* __restrict__ out)
{
    extern __shared__ __align__(16) char dynsm[];
    __nv_bfloat16* Ah = (__nv_bfloat16*)dynsm;
    __nv_bfloat16* Al = Ah + 128 * LDA;
    __nv_bfloat16* Bh = Al + 128 * LDA;
    __nv_bfloat16* Bl = Bh + 128 * LDB;
    float* F = (float*)dynsm;                 // fp32 tile [128][FLD], aliases bf16 stage
    __shared__ int s_nl[128];
    __shared__ int s_t;
    __shared__ float s_scp[128];

    int tid = threadIdx.x, w = tid >> 5, lane = tid & 31;
    if (tid < 128) s_nl[tid] = g_nlist[blockIdx.x * 128 + tid];
    __syncthreads();
    if (tid == 0) {
        int t = -1;
        for (int m = 0; m < 128; m++) if (s_nl[m] >= 0) { t = ntype[s_nl[m]]; break; }
        s_t = t;
    }
    if (tid < 128) {
        int n = s_nl[tid];
        float inv = 1.f;
        if (n >= 0) {
            int cp = 0;
            for (int r = 0; r < RR; r++) cp += (g_den[(n * RR + r) * HH] > 0.f) ? 1 : 0;
            if (cp < 1) cp = 1;
            inv = 1.f / (float)cp;
        }
        s_scp[tid] = inv;
    }
    __syncthreads();
    if (s_t < 0) return;

    // stage A: T = g_acc * scp, split bf16 hi/lo
    for (int idx = tid; idx < 128 * 32; idx += 256) {
        int m = idx >> 5, c = (idx & 31) * 4;
        int n = s_nl[m];
        float4 f = make_float4(0.f, 0.f, 0.f, 0.f);
        if (n >= 0) {
            f = *(const float4*)(g_acc + (size_t)n * FDIM + c);
            float sc = s_scp[m];
            f.x *= sc; f.y *= sc; f.z *= sc; f.w *= sc;
        }
        uint32_t l0, l1;
        uint32_t h0 = bfsplit(f.x, f.y, l0), h1 = bfsplit(f.z, f.w, l1);
        *(uint32_t*)(Ah + m * LDA + c)     = h0;
        *(uint32_t*)(Ah + m * LDA + c + 2) = h1;
        *(uint32_t*)(Al + m * LDA + c)     = l0;
        *(uint32_t*)(Al + m * LDA + c + 2) = l1;
    }
    // stage B: Wa[t]
    {
        const float* W = Wa + s_t * FDIM * FDIM;
        for (int idx = tid; idx < 128 * 32; idx += 256) {
            int kk = idx >> 5, c = (idx & 31) * 4;
            float4 f = *(const float4*)(W + kk * FDIM + c);
            uint32_t l0, l1;
            uint32_t h0 = bfsplit(f.x, f.y, l0), h1 = bfsplit(f.z, f.w, l1);
            *(uint32_t*)(Bh + kk * LDB + c)     = h0;
            *(uint32_t*)(Bh + kk * LDB + c + 2) = h1;
            *(uint32_t*)(Bl + kk * LDB + c)     = l0;
            *(uint32_t*)(Bl + kk * LDB + c + 2) = l1;
        }
    }
    __syncthreads();

    int row_m = w * 16;
    wmma::fragment<wmma::accumulator, 16, 16, 16, float> acc[8];
    #pragma unroll
    for (int ni = 0; ni < 8; ni++) wmma::fill_fragment(acc[ni], 0.f);
    for (int k = 0; k < 8; k++) {
        wmma::fragment<wmma::matrix_a, 16, 16, 16, __nv_bfloat16, wmma::row_major> ah, al;
        wmma::load_matrix_sync(ah, Ah + row_m * LDA + k * 16, LDA);
        wmma::load_matrix_sync(al, Al + row_m * LDA + k * 16, LDA);
        #pragma unroll
        for (int ni = 0; ni < 8; ni++) {
            wmma::fragment<wmma::matrix_b, 16, 16, 16, __nv_bfloat16, wmma::row_major> bh, bl;
            wmma::load_matrix_sync(bh, Bh + (k * 16) * LDB + ni * 16, LDB);
            wmma::load_matrix_sync(bl, Bl + (k * 16) * LDB + ni * 16, LDB);
            wmma::mma_sync(acc[ni], ah, bh, acc[ni]);
            wmma::mma_sync(acc[ni], ah, bl, acc[ni]);
            wmma::mma_sync(acc[ni], al, bh, acc[ni]);
        }
    }
    __syncthreads();   // all bf16 stage reads done; F may alias

    #pragma unroll
    for (int ni = 0; ni < 8; ni++)
        wmma::store_matrix_sync(F + row_m * FLD + ni * 16, acc[ni], FLD, wmma::mem_row_major);
    __syncwarp();

    // epilogue: skip blend + per-type LN; warp w handles rows row_m..row_m+15
    float alpha = 1.f / (1.f + __expf(-skipv[s_t]));
    float beta = 1.f - alpha;
    int c0 = lane * 4;
    float4 bav = *(const float4*)(ba   + s_t * FDIM + c0);
    float4 gv  = *(const float4*)(ln_g + s_t * FDIM + c0);
    float4 bv2 = *(const float4*)(ln_b + s_t * FDIM + c0);
    for (int q = 0; q < 16; q++) {
        int m = row_m + q;
        int n = s_nl[m];
        if (n < 0) continue;
        float4 tr = *(float4*)(F + m * FLD + c0);
        float4 xv = *(const float4*)(x + (size_t)n * FDIM + c0);
        float4 v;
        v.x = (tr.x + bav.x) * alpha + xv.x * beta;
        v.y = (tr.y + bav.y) * alpha + xv.y * beta;
        v.z = (tr.z + bav.z) * alpha + xv.z * beta;
        v.w = (tr.w + bav.w) * alpha + xv.w * beta;
        float s  = v.x + v.y + v.z + v.w;
        float s2 = v.x*v.x + v.y*v.y + v.z*v.z + v.w*v.w;
        #pragma unroll
        for (int o = 16; o; o >>= 1) {
            s  += __shfl_xor_sync(0xFFFFFFFFu, s,  o);
            s2 += __shfl_xor_sync(0xFFFFFFFFu, s2, o);
        }
        float mu = s * (1.f / 128.f);
        float var = s2 * (1.f / 128.f) - mu * mu;
        float rstd = rsqrtf(var + 1e-5f);
        float4 ov;
        ov.x = (v.x - mu) * rstd * gv.x + bv2.x;
        ov.y = (v.y - mu) * rstd * gv.y + bv2.y;
        ov.z = (v.z - mu) * rstd * gv.z + bv2.z;
        ov.w = (v.w - mu) * rstd * gv.w + bv2.w;
        *(float4*)(out + (size_t)n * FDIM + c0) = ov;
    }
}

// ---------------- launch ----------------
extern "C" void kernel_launch(void* const* d_in, const int* in_sizes, int n_in,
                              void* d_out, int out_size) {
    const float* x       = (const float*)d_in[0];
    const int*   ntype   = (const int*)  d_in[1];
    const int*   src     = (const int*)  d_in[2];
    const int*   dst     = (const int*)  d_in[3];
    const int*   etype   = (const int*)  d_in[4];
    const float* Wk      = (const float*)d_in[5];
    const float* bk      = (const float*)d_in[6];
    const float* Wq      = (const float*)d_in[7];
    const float* bq      = (const float*)d_in[8];
    const float* Wv      = (const float*)d_in[9];
    const float* bv      = (const float*)d_in[10];
    const float* Wa      = (const float*)d_in[11];
    const float* ba      = (const float*)d_in[12];
    const float* rel_pri = (const float*)d_in[13];
    const float* rel_att = (const float*)d_in[14];
    const float* rel_msg = (const float*)d_in[15];
    const float* skipv   = (const float*)d_in[16];
    const float* ln_g    = (const float*)d_in[17];
    const float* ln_b    = (const float*)d_in[18];
    float* out = (float*)d_out;

    const int N = in_sizes[1];
    const int E = in_sizes[2];
    const int PROJ_SMEM = 4 * 128 * LDA * 2;   // 139264 B

    cudaFuncSetAttribute(proj_wmma_kernel,  cudaFuncAttributeMaxDynamicSharedMemorySize, PROJ_SMEM);
    cudaFuncSetAttribute(final_wmma_kernel, cudaFuncAttributeMaxDynamicSharedMemorySize, PROJ_SMEM);

    zero_kernel<<<4096, 256>>>();
    hist_kernel<<<(N + 255) / 256, 256>>>(ntype, N);
    ehist_kernel<<<(E + 255) / 256, 256>>>(etype, E);
    scan_kernel<<<1, 32>>>();
    scatter_kernel<<<(N + 255) / 256, 256>>>(ntype, N);
    escatter_kernel<<<(E + 255) / 256, 256>>>(src, dst, etype, E);
    proj_wmma_kernel<<<NL_CAP / 128, 256, PROJ_SMEM>>>(x, ntype, Wk, bk, Wq, bq, Wv, bv);
    score_kernel<<<2048, 256>>>(rel_pri, rel_att, E);
    agg_kernel<<<2048, 256>>>(rel_msg, E);
    final_wmma_kernel<<<NL_CAP / 128, 256, PROJ_SMEM>>>(x, ntype, Wa, ba, skipv, ln_g, ln_b, out);
}

// round 7
// speedup vs baseline: 1.1468x; 1.1468x over previous
#include <cuda_runtime.h>
#include <cuda_bf16.h>
#include <mma.h>
#include <stdint.h>
#include <math.h>

using namespace nvcuda;

// Problem constants (AttentionLayer_11776800325798)
#define NMAX   50000
#define EMAX   500000
#define TT     3
#define RR     5
#define HH     8
#define DKK    16
#define FDIM   128
#define NRH    (NMAX * RR * HH)                      // 2,000,000
#define NL_CAP (((NMAX / 128) + TT + 1) * 128)       // 50432, 128-padded per type
#define SQRT_DK 4.0f
#define MATPAD 272                                   // SMEM matrix stride (floats)
#define LDA 136                                      // bf16 elems per row (128 + 8 pad)
#define LDB 136
#define FLD 132                                      // fp32 staging tile stride

// ---------------- scratch (static __device__, no allocation) ----------------
__device__ float    g_k[NMAX * FDIM];
__device__ float    g_q[NMAX * FDIM];
__device__ float    g_v[NMAX * FDIM];
__device__ float    g_acc[NMAX * FDIM];
__device__ float    g_a[EMAX * HH];
__device__ float    g_den[NRH];
__device__ int      g_nlist[NL_CAP];
__device__ int      g_cur[TT];
__device__ int      g_poff[TT + 1];
// pre-converted weights: [type][set(k,q,v,a)][hi|lo] each 128x128 bf16 row-major (32KB)
__device__ __align__(16) unsigned char g_wB[TT * 4 * 2 * 32768];

// fp32 -> bf16 hi + bf16 lo (packed pairs)
__device__ __forceinline__ uint32_t bfsplit(float a, float b, uint32_t& lo) {
    __nv_bfloat162 h = __floats2bfloat162_rn(a, b);
    float ra = a - __bfloat162float(h.x);
    float rb = b - __bfloat162float(h.y);
    __nv_bfloat162 l = __floats2bfloat162_rn(ra, rb);
    lo = *reinterpret_cast<uint32_t*>(&l);
    return *reinterpret_cast<uint32_t*>(&h);
}

// ============================================================================
// K1: prep — fused counter zero + type histogram + scan + nlist init (1 block)
// ============================================================================
__global__ __launch_bounds__(1024) void prep_kernel(const int* __restrict__ ntype, int N) {
    __shared__ int scnt[TT];
    int tid = threadIdx.x;
    if (tid < TT) scnt[tid] = 0;
    __syncthreads();
    int c0 = 0, c1 = 0, c2 = 0;
    for (int i = tid; i < N; i += 1024) {
        int t = ntype[i];
        c0 += (t == 0); c1 += (t == 1); c2 += (t == 2);
    }
    if (c0) atomicAdd(&scnt[0], c0);
    if (c1) atomicAdd(&scnt[1], c1);
    if (c2) atomicAdd(&scnt[2], c2);
    __syncthreads();
    if (tid == 0) {
        int o = 0;
        for (int t = 0; t < TT; t++) { g_poff[t] = o; o += ((scnt[t] + 127) / 128) * 128; }
        g_poff[TT] = o;
    }
    if (tid < TT) g_cur[tid] = 0;
    for (int i = tid; i < NL_CAP; i += 1024) g_nlist[i] = -1;
}

// ============================================================================
// K2: scatter nodes into type-sorted, 128-padded list (warp-aggregated)
// ============================================================================
__global__ void scatter_kernel(const int* __restrict__ ntype, int N) {
    int i = blockIdx.x * blockDim.x + threadIdx.x;
    int t = (i < N) ? ntype[i] : -1;
    #pragma unroll
    for (int tt = 0; tt < TT; tt++) {
        unsigned mask = __ballot_sync(0xFFFFFFFFu, t == tt);
        if (t == tt) {
            int lane = threadIdx.x & 31;
            int leader = __ffs(mask) - 1;
            int rank = __popc(mask & ((1u << lane) - 1));
            int base = 0;
            if (lane == leader) base = atomicAdd(&g_cur[tt], __popc(mask));
            base = __shfl_sync(mask, base, leader);
            g_nlist[g_poff[tt] + base + rank] = i;
        }
    }
}

// ============================================================================
// K3: weight pre-conversion: all 4 W sets -> bf16 hi/lo row-major [128][128]
// ============================================================================
__global__ void wconv_kernel(const float* __restrict__ Wk, const float* __restrict__ Wq,
                             const float* __restrict__ Wv, const float* __restrict__ Wa) {
    int idx = blockIdx.x * blockDim.x + threadIdx.x;
    if (idx >= TT * 4 * 128 * 32) return;          // 49152 threads: one per 4-float group
    int c = (idx & 31) * 4;                        // col 0..124
    int kk = (idx >> 5) & 127;                     // row (input dim k)
    int g = idx >> 12;                             // 0..11 = t*4+set
    int set = g & 3, t = g >> 2;
    const float* W = ((set == 0) ? Wk : (set == 1) ? Wq : (set == 2) ? Wv : Wa) + t * FDIM * FDIM;
    float4 f = *(const float4*)(W + kk * FDIM + c);
    uint32_t l0, l1;
    uint32_t h0 = bfsplit(f.x, f.y, l0), h1 = bfsplit(f.z, f.w, l1);
    __nv_bfloat16* hi = (__nv_bfloat16*)(g_wB + (size_t)g * 65536);
    __nv_bfloat16* lo = hi + 128 * 128;
    *(uint32_t*)(hi + kk * 128 + c)     = h0;
    *(uint32_t*)(hi + kk * 128 + c + 2) = h1;
    *(uint32_t*)(lo + kk * 128 + c)     = l0;
    *(uint32_t*)(lo + kk * 128 + c + 2) = l1;
}

// ============================================================================
// K4: typed projections via wmma bf16 split (fp32-accurate)   [PROFILED SLOT]
// ============================================================================
__global__ __launch_bounds__(256) void proj_wmma_kernel(
    const float* __restrict__ x, const int* __restrict__ ntype,
    const float* __restrict__ bk, const float* __restrict__ bq,
    const float* __restrict__ bv)
{
    extern __shared__ __align__(16) char dynsm[];
    __nv_bfloat16* Ah = (__nv_bfloat16*)dynsm;
    __nv_bfloat16* Al = Ah + 128 * LDA;
    __nv_bfloat16* Bh = Al + 128 * LDA;
    __nv_bfloat16* Bl = Bh + 128 * LDB;
    __shared__ int s_nl[128];
    __shared__ int s_t;
    __shared__ __align__(16) float stg[8][16][24];

    int tid = threadIdx.x, w = tid >> 5, lane = tid & 31;
    if (tid < 128) s_nl[tid] = g_nlist[blockIdx.x * 128 + tid];
    __syncthreads();
    if (tid == 0) {
        int t = -1;
        for (int m = 0; m < 128; m++) if (s_nl[m] >= 0) { t = ntype[s_nl[m]]; break; }
        s_t = t;
    }
    __syncthreads();
    if (s_t < 0) return;

    // stage A: gather x rows, split into bf16 hi/lo
    for (int idx = tid; idx < 128 * 32; idx += 256) {
        int m = idx >> 5, c = (idx & 31) * 4;
        int n = s_nl[m];
        float4 f = (n >= 0) ? *(const float4*)(x + (size_t)n * FDIM + c)
                            : make_float4(0.f, 0.f, 0.f, 0.f);
        uint32_t l0, l1;
        uint32_t h0 = bfsplit(f.x, f.y, l0), h1 = bfsplit(f.z, f.w, l1);
        *(uint32_t*)(Ah + m * LDA + c)     = h0;
        *(uint32_t*)(Ah + m * LDA + c + 2) = h1;
        *(uint32_t*)(Al + m * LDA + c)     = l0;
        *(uint32_t*)(Al + m * LDA + c + 2) = l1;
    }

    int row_m = w * 16;
    int r = lane >> 1, c0 = (lane & 1) * 8;
    int gr = s_nl[row_m + r];

    for (int set = 0; set < 3; set++) {
        // stage B: copy pre-converted bf16 hi/lo (64KB) into padded SMEM
        const uint4* hsrc = (const uint4*)(g_wB + (size_t)(s_t * 4 + set) * 65536);
        const uint4* lsrc = hsrc + 2048;
        for (int idx = tid; idx < 2048; idx += 256) {
            int row = idx >> 4, u4 = idx & 15;
            *(uint4*)(Bh + row * LDB + u4 * 8) = hsrc[idx];
            *(uint4*)(Bl + row * LDB + u4 * 8) = lsrc[idx];
        }
        __syncthreads();

        wmma::fragment<wmma::accumulator, 16, 16, 16, float> acc[8];
        #pragma unroll
        for (int ni = 0; ni < 8; ni++) wmma::fill_fragment(acc[ni], 0.f);
        for (int k = 0; k < 8; k++) {
            wmma::fragment<wmma::matrix_a, 16, 16, 16, __nv_bfloat16, wmma::row_major> ah, al;
            wmma::load_matrix_sync(ah, Ah + row_m * LDA + k * 16, LDA);
            wmma::load_matrix_sync(al, Al + row_m * LDA + k * 16, LDA);
            #pragma unroll
            for (int ni = 0; ni < 8; ni++) {
                wmma::fragment<wmma::matrix_b, 16, 16, 16, __nv_bfloat16, wmma::row_major> bh, bl;
                wmma::load_matrix_sync(bh, Bh + (k * 16) * LDB + ni * 16, LDB);
                wmma::load_matrix_sync(bl, Bl + (k * 16) * LDB + ni * 16, LDB);
                wmma::mma_sync(acc[ni], ah, bh, acc[ni]);
                wmma::mma_sync(acc[ni], ah, bl, acc[ni]);
                wmma::mma_sync(acc[ni], al, bh, acc[ni]);
            }
        }

        float* ob = (set == 0) ? g_k : (set == 1) ? g_q : g_v;
        const float* bias = ((set == 0) ? bk : (set == 1) ? bq : bv) + s_t * FDIM;
        for (int ni = 0; ni < 8; ni++) {
            wmma::store_matrix_sync(&stg[w][0][0], acc[ni], 24, wmma::mem_row_major);
            __syncwarp();
            if (gr >= 0) {
                int col = ni * 16 + c0;
                float4 v0 = *(float4*)&stg[w][r][c0];
                float4 v1 = *(float4*)&stg[w][r][c0 + 4];
                v0.x += bias[col + 0]; v0.y += bias[col + 1];
                v0.z += bias[col + 2]; v0.w += bias[col + 3];
                v1.x += bias[col + 4]; v1.y += bias[col + 5];
                v1.z += bias[col + 6]; v1.w += bias[col + 7];
                *(float4*)(ob + (size_t)gr * FDIM + col)     = v0;
                *(float4*)(ob + (size_t)gr * FDIM + col + 4) = v1;
            }
            __syncwarp();
        }
        __syncthreads();
    }
}

// ============================================================================
// K5: zero accumulators (g_acc, g_den) — placed after proj, before score
// ============================================================================
__global__ void zero_kernel() {
    int stride = gridDim.x * blockDim.x;
    for (int idx = blockIdx.x * blockDim.x + threadIdx.x; idx < NMAX * FDIM; idx += stride) {
        g_acc[idx] = 0.f;
        if (idx < NRH) g_den[idx] = 0.f;
    }
}

// ============================================================================
// K6: edge scores + exp + segment denom (R5-proven version)
// ============================================================================
__global__ __launch_bounds__(256) void score_kernel(
    const int* __restrict__ src, const int* __restrict__ dst,
    const int* __restrict__ etype,
    const float* __restrict__ rel_pri, const float* __restrict__ rel_att, int E) {
    __shared__ __align__(16) float s_att[RR * HH * MATPAD];
    __shared__ float s_pri[RR * HH];
    for (int idx = threadIdx.x; idx < RR * HH * DKK * DKK; idx += 256) {
        int mat = idx >> 8, inner = idx & 255;
        s_att[mat * MATPAD + inner] = rel_att[idx];
    }
    if (threadIdx.x < RR * HH) s_pri[threadIdx.x] = rel_pri[threadIdx.x];
    __syncthreads();

    int warp = threadIdx.x >> 5;
    int lane = threadIdx.x & 31;
    int h = lane >> 2, qq = lane & 3;
    for (int e = blockIdx.x * 8 + warp; e < E; e += gridDim.x * 8) {
        int s = src[e], d = dst[e], r = etype[e];
        const float4* kp = (const float4*)(g_k + s * FDIM + h * DKK);
        float kr[16];
        #pragma unroll
        for (int i = 0; i < 4; i++) {
            float4 kv = kp[i];
            kr[i*4+0]=kv.x; kr[i*4+1]=kv.y; kr[i*4+2]=kv.z; kr[i*4+3]=kv.w;
        }
        float4 qv = *(const float4*)(g_q + d * FDIM + h * DKK + qq * 4);
        const float* A = s_att + (r * HH + h) * MATPAD + qq * 4;
        float4 t = make_float4(0.f, 0.f, 0.f, 0.f);
        #pragma unroll
        for (int dd = 0; dd < 16; dd++) {
            float4 av = *(const float4*)(A + dd * DKK);
            float kc = kr[dd];
            t.x = fmaf(kc, av.x, t.x);
            t.y = fmaf(kc, av.y, t.y);
            t.z = fmaf(kc, av.z, t.z);
            t.w = fmaf(kc, av.w, t.w);
        }
        float sc = t.x*qv.x + t.y*qv.y + t.z*qv.z + t.w*qv.w;
        sc += __shfl_xor_sync(0xFFFFFFFFu, sc, 1);
        sc += __shfl_xor_sync(0xFFFFFFFFu, sc, 2);
        sc *= s_pri[r * HH + h] * (1.0f / SQRT_DK);
        if (qq == 0) {
            float p = __expf(sc);
            g_a[e * HH + h] = p;
            atomicAdd(&g_den[(d * RR + r) * HH + h], p);
        }
    }
}

// ============================================================================
// K7: weighted message aggregation (R5-proven version)
// ============================================================================
__global__ __launch_bounds__(256) void agg_kernel(
    const int* __restrict__ src, const int* __restrict__ dst,
    const int* __restrict__ etype, const float* __restrict__ rel_msg, int E) {
    __shared__ __align__(16) float s_msg[RR * HH * MATPAD];
    for (int idx = threadIdx.x; idx < RR * HH * DKK * DKK; idx += 256) {
        int mat = idx >> 8, inner = idx & 255;
        s_msg[mat * MATPAD + inner] = rel_msg[idx];
    }
    __syncthreads();

    int warp = threadIdx.x >> 5;
    int lane = threadIdx.x & 31;
    int h = lane >> 2, qq = lane & 3;
    for (int e = blockIdx.x * 8 + warp; e < E; e += gridDim.x * 8) {
        int s = src[e], d = dst[e], r = etype[e];
        float p = g_a[e * HH + h];
        float den = g_den[(d * RR + r) * HH + h];
        float attw = p / den;
        const float4* vp = (const float4*)(g_v + s * FDIM + h * DKK);
        float vr[16];
        #pragma unroll
        for (int i = 0; i < 4; i++) {
            float4 vv = vp[i];
            vr[i*4+0]=vv.x; vr[i*4+1]=vv.y; vr[i*4+2]=vv.z; vr[i*4+3]=vv.w;
        }
        const float* M = s_msg + (r * HH + h) * MATPAD + qq * 4;
        float4 o = make_float4(0.f, 0.f, 0.f, 0.f);
        #pragma unroll
        for (int dd = 0; dd < 16; dd++) {
            float4 mv = *(const float4*)(M + dd * DKK);
            float vc = vr[dd];
            o.x = fmaf(vc, mv.x, o.x);
            o.y = fmaf(vc, mv.y, o.y);
            o.z = fmaf(vc, mv.z, o.z);
            o.w = fmaf(vc, mv.w, o.w);
        }
        float4 add = make_float4(attw*o.x, attw*o.y, attw*o.z, attw*o.w);
        atomicAdd((float4*)(g_acc + d * FDIM + h * DKK + qq * 4), add);
    }
}

// ============================================================================
// K8: mean-over-etypes, Wa proj (wmma split-bf16), skip blend, per-type LN
// ============================================================================
__global__ __launch_bounds__(256) void final_wmma_kernel(
    const float* __restrict__ x, const int* __restrict__ ntype,
    const float* __restrict__ ba, const float* __restrict__ skipv,
    const float* __restrict__ ln_g, const float* __restrict__ ln_b,
    float* __restrict__ out)
{
    extern __shared__ __align__(16) char dynsm[];
    __nv_bfloat16* Ah = (__nv_bfloat16*)dynsm;
    __nv_bfloat16* Al = Ah + 128 * LDA;
    __nv_bfloat16* Bh = Al + 128 * LDA;
    __nv_bfloat16* Bl = Bh + 128 * LDB;
    float* F = (float*)dynsm;                 // fp32 tile [128][FLD], aliases bf16 stage
    __shared__ int s_nl[128];
    __shared__ int s_t;
    __shared__ float s_scp[128];

    int tid = threadIdx.x, w = tid >> 5, lane = tid & 31;
    if (tid < 128) s_nl[tid] = g_nlist[blockIdx.x * 128 + tid];
    __syncthreads();
    if (tid == 0) {
        int t = -1;
        for (int m = 0; m < 128; m++) if (s_nl[m] >= 0) { t = ntype[s_nl[m]]; break; }
        s_t = t;
    }
    if (tid < 128) {
        int n = s_nl[tid];
        float inv = 1.f;
        if (n >= 0) {
            int cp = 0;
            for (int r = 0; r < RR; r++) cp += (g_den[(n * RR + r) * HH] > 0.f) ? 1 : 0;
            if (cp < 1) cp = 1;
            inv = 1.f / (float)cp;
        }
        s_scp[tid] = inv;
    }
    __syncthreads();
    if (s_t < 0) return;

    // stage A: T = g_acc * scp, split bf16 hi/lo
    for (int idx = tid; idx < 128 * 32; idx += 256) {
        int m = idx >> 5, c = (idx & 31) * 4;
        int n = s_nl[m];
        float4 f = make_float4(0.f, 0.f, 0.f, 0.f);
        if (n >= 0) {
            f = *(const float4*)(g_acc + (size_t)n * FDIM + c);
            float sc = s_scp[m];
            f.x *= sc; f.y *= sc; f.z *= sc; f.w *= sc;
        }
        uint32_t l0, l1;
        uint32_t h0 = bfsplit(f.x, f.y, l0), h1 = bfsplit(f.z, f.w, l1);
        *(uint32_t*)(Ah + m * LDA + c)     = h0;
        *(uint32_t*)(Ah + m * LDA + c + 2) = h1;
        *(uint32_t*)(Al + m * LDA + c)     = l0;
        *(uint32_t*)(Al + m * LDA + c + 2) = l1;
    }
    // stage B: Wa[t] pre-converted
    {
        const uint4* hsrc = (const uint4*)(g_wB + (size_t)(s_t * 4 + 3) * 65536);
        const uint4* lsrc = hsrc + 2048;
        for (int idx = tid; idx < 2048; idx += 256) {
            int row = idx >> 4, u4 = idx & 15;
            *(uint4*)(Bh + row * LDB + u4 * 8) = hsrc[idx];
            *(uint4*)(Bl + row * LDB + u4 * 8) = lsrc[idx];
        }
    }
    __syncthreads();

    int row_m = w * 16;
    wmma::fragment<wmma::accumulator, 16, 16, 16, float> acc[8];
    #pragma unroll
    for (int ni = 0; ni < 8; ni++) wmma::fill_fragment(acc[ni], 0.f);
    for (int k = 0; k < 8; k++) {
        wmma::fragment<wmma::matrix_a, 16, 16, 16, __nv_bfloat16, wmma::row_major> ah, al;
        wmma::load_matrix_sync(ah, Ah + row_m * LDA + k * 16, LDA);
        wmma::load_matrix_sync(al, Al + row_m * LDA + k * 16, LDA);
        #pragma unroll
        for (int ni = 0; ni < 8; ni++) {
            wmma::fragment<wmma::matrix_b, 16, 16, 16, __nv_bfloat16, wmma::row_major> bh, bl;
            wmma::load_matrix_sync(bh, Bh + (k * 16) * LDB + ni * 16, LDB);
            wmma::load_matrix_sync(bl, Bl + (k * 16) * LDB + ni * 16, LDB);
            wmma::mma_sync(acc[ni], ah, bh, acc[ni]);
            wmma::mma_sync(acc[ni], ah, bl, acc[ni]);
            wmma::mma_sync(acc[ni], al, bh, acc[ni]);
        }
    }
    __syncthreads();   // all bf16 stage reads done; F may alias

    #pragma unroll
    for (int ni = 0; ni < 8; ni++)
        wmma::store_matrix_sync(F + row_m * FLD + ni * 16, acc[ni], FLD, wmma::mem_row_major);
    __syncwarp();

    float alpha = 1.f / (1.f + __expf(-skipv[s_t]));
    float beta = 1.f - alpha;
    int c0 = lane * 4;
    float4 bav = *(const float4*)(ba   + s_t * FDIM + c0);
    float4 gv  = *(const float4*)(ln_g + s_t * FDIM + c0);
    float4 bv2 = *(const float4*)(ln_b + s_t * FDIM + c0);
    for (int q = 0; q < 16; q++) {
        int m = row_m + q;
        int n = s_nl[m];
        if (n < 0) continue;
        float4 tr = *(float4*)(F + m * FLD + c0);
        float4 xv = *(const float4*)(x + (size_t)n * FDIM + c0);
        float4 v;
        v.x = (tr.x + bav.x) * alpha + xv.x * beta;
        v.y = (tr.y + bav.y) * alpha + xv.y * beta;
        v.z = (tr.z + bav.z) * alpha + xv.z * beta;
        v.w = (tr.w + bav.w) * alpha + xv.w * beta;
        float s  = v.x + v.y + v.z + v.w;
        float s2 = v.x*v.x + v.y*v.y + v.z*v.z + v.w*v.w;
        #pragma unroll
        for (int o = 16; o; o >>= 1) {
            s  += __shfl_xor_sync(0xFFFFFFFFu, s,  o);
            s2 += __shfl_xor_sync(0xFFFFFFFFu, s2, o);
        }
        float mu = s * (1.f / 128.f);
        float var = s2 * (1.f / 128.f) - mu * mu;
        float rstd = rsqrtf(var + 1e-5f);
        float4 ov;
        ov.x = (v.x - mu) * rstd * gv.x + bv2.x;
        ov.y = (v.y - mu) * rstd * gv.y + bv2.y;
        ov.z = (v.z - mu) * rstd * gv.z + bv2.z;
        ov.w = (v.w - mu) * rstd * gv.w + bv2.w;
        *(float4*)(out + (size_t)n * FDIM + c0) = ov;
    }
}

// ---------------- launch ----------------
extern "C" void kernel_launch(void* const* d_in, const int* in_sizes, int n_in,
                              void* d_out, int out_size) {
    const float* x       = (const float*)d_in[0];
    const int*   ntype   = (const int*)  d_in[1];
    const int*   src     = (const int*)  d_in[2];
    const int*   dst     = (const int*)  d_in[3];
    const int*   etype   = (const int*)  d_in[4];
    const float* Wk      = (const float*)d_in[5];
    const float* bk      = (const float*)d_in[6];
    const float* Wq      = (const float*)d_in[7];
    const float* bq      = (const float*)d_in[8];
    const float* Wv      = (const float*)d_in[9];
    const float* bv      = (const float*)d_in[10];
    const float* Wa      = (const float*)d_in[11];
    const float* ba      = (const float*)d_in[12];
    const float* rel_pri = (const float*)d_in[13];
    const float* rel_att = (const float*)d_in[14];
    const float* rel_msg = (const float*)d_in[15];
    const float* skipv   = (const float*)d_in[16];
    const float* ln_g    = (const float*)d_in[17];
    const float* ln_b    = (const float*)d_in[18];
    float* out = (float*)d_out;

    const int N = in_sizes[1];
    const int E = in_sizes[2];
    const int PROJ_SMEM = 4 * 128 * LDA * 2;   // 139264 B

    cudaFuncSetAttribute(proj_wmma_kernel,  cudaFuncAttributeMaxDynamicSharedMemorySize, PROJ_SMEM);
    cudaFuncSetAttribute(final_wmma_kernel, cudaFuncAttributeMaxDynamicSharedMemorySize, PROJ_SMEM);

    prep_kernel<<<1, 1024>>>(ntype, N);
    scatter_kernel<<<(N + 255) / 256, 256>>>(ntype, N);
    wconv_kernel<<<(TT * 4 * 128 * 32 + 255) / 256, 256>>>(Wk, Wq, Wv, Wa);
    proj_wmma_kernel<<<NL_CAP / 128, 256, PROJ_SMEM>>>(x, ntype, bk, bq, bv);   // profiled slot
    zero_kernel<<<4096, 256>>>();
    score_kernel<<<2048, 256>>>(src, dst, etype, rel_pri, rel_att, E);
    agg_kernel<<<2048, 256>>>(src, dst, etype, rel_msg, E);
    final_wmma_kernel<<<NL_CAP / 128, 256, PROJ_SMEM>>>(x, ntype, ba, skipv, ln_g, ln_b, out);
}

// round 8
// speedup vs baseline: 1.1768x; 1.0261x over previous
#include <cuda_runtime.h>
#include <cuda_bf16.h>
#include <mma.h>
#include <stdint.h>
#include <math.h>

using namespace nvcuda;

// Problem constants (AttentionLayer_11776800325798)
#define NMAX   50000
#define EMAX   500000
#define TT     3
#define RR     5
#define HH     8
#define DKK    16
#define FDIM   128
#define NRH    (NMAX * RR * HH)                      // 2,000,000
#define NL_CAP (((NMAX / 128) + TT + 1) * 128)       // 50432, 128-padded per type
#define SQRT_DK 4.0f
#define LDA 136                                      // bf16 elems per row (128 + 8 pad)
#define LDB 136
#define FLD 132                                      // fp32 staging tile stride

// ---------------- scratch (static __device__, no allocation) ----------------
__device__ __nv_bfloat16 g_kb[NMAX * FDIM];
__device__ __nv_bfloat16 g_qb[NMAX * FDIM];
__device__ __nv_bfloat16 g_vb[NMAX * FDIM];
__device__ float    g_acc[NMAX * FDIM];
__device__ float    g_a[EMAX * HH];
__device__ float    g_den[NRH];
__device__ int      g_nlist[NL_CAP];
__device__ int      g_cur[TT];
__device__ int      g_poff[TT + 1];
// pre-converted weights: [type][set(k,q,v,a)][hi|lo] each 128x128 bf16 row-major (32KB)
__device__ __align__(16) unsigned char g_wB[TT * 4 * 2 * 32768];

// fp32 -> bf16 hi + bf16 lo (packed pairs)
__device__ __forceinline__ uint32_t bfsplit(float a, float b, uint32_t& lo) {
    __nv_bfloat162 h = __floats2bfloat162_rn(a, b);
    float ra = a - __bfloat162float(h.x);
    float rb = b - __bfloat162float(h.y);
    __nv_bfloat162 l = __floats2bfloat162_rn(ra, rb);
    lo = *reinterpret_cast<uint32_t*>(&l);
    return *reinterpret_cast<uint32_t*>(&h);
}
__device__ __forceinline__ float2 bf2f2(uint32_t u) {
    __nv_bfloat162 b = *reinterpret_cast<__nv_bfloat162*>(&u);
    return __bfloat1622float2(b);
}

// ============================================================================
// K1: prep — fused counter zero + type histogram + scan + nlist init (1 block)
// ============================================================================
__global__ __launch_bounds__(1024) void prep_kernel(const int* __restrict__ ntype, int N) {
    __shared__ int scnt[TT];
    int tid = threadIdx.x;
    if (tid < TT) scnt[tid] = 0;
    __syncthreads();
    int c0 = 0, c1 = 0, c2 = 0;
    for (int i = tid; i < N; i += 1024) {
        int t = ntype[i];
        c0 += (t == 0); c1 += (t == 1); c2 += (t == 2);
    }
    if (c0) atomicAdd(&scnt[0], c0);
    if (c1) atomicAdd(&scnt[1], c1);
    if (c2) atomicAdd(&scnt[2], c2);
    __syncthreads();
    if (tid == 0) {
        int o = 0;
        for (int t = 0; t < TT; t++) { g_poff[t] = o; o += ((scnt[t] + 127) / 128) * 128; }
        g_poff[TT] = o;
    }
    if (tid < TT) g_cur[tid] = 0;
    for (int i = tid; i < NL_CAP; i += 1024) g_nlist[i] = -1;
}

// ============================================================================
// K2: scatter nodes into type-sorted, 128-padded list (warp-aggregated)
// ============================================================================
__global__ void scatter_kernel(const int* __restrict__ ntype, int N) {
    int i = blockIdx.x * blockDim.x + threadIdx.x;
    int t = (i < N) ? ntype[i] : -1;
    #pragma unroll
    for (int tt = 0; tt < TT; tt++) {
        unsigned mask = __ballot_sync(0xFFFFFFFFu, t == tt);
        if (t == tt) {
            int lane = threadIdx.x & 31;
            int leader = __ffs(mask) - 1;
            int rank = __popc(mask & ((1u << lane) - 1));
            int base = 0;
            if (lane == leader) base = atomicAdd(&g_cur[tt], __popc(mask));
            base = __shfl_sync(mask, base, leader);
            g_nlist[g_poff[tt] + base + rank] = i;
        }
    }
}

// ============================================================================
// K3: weight pre-conversion: all 4 W sets -> bf16 hi/lo row-major [128][128]
// ============================================================================
__global__ void wconv_kernel(const float* __restrict__ Wk, const float* __restrict__ Wq,
                             const float* __restrict__ Wv, const float* __restrict__ Wa) {
    int idx = blockIdx.x * blockDim.x + threadIdx.x;
    if (idx >= TT * 4 * 128 * 32) return;
    int c = (idx & 31) * 4;
    int kk = (idx >> 5) & 127;
    int g = idx >> 12;                             // 0..11 = t*4+set
    int set = g & 3, t = g >> 2;
    const float* W = ((set == 0) ? Wk : (set == 1) ? Wq : (set == 2) ? Wv : Wa) + t * FDIM * FDIM;
    float4 f = *(const float4*)(W + kk * FDIM + c);
    uint32_t l0, l1;
    uint32_t h0 = bfsplit(f.x, f.y, l0), h1 = bfsplit(f.z, f.w, l1);
    __nv_bfloat16* hi = (__nv_bfloat16*)(g_wB + (size_t)g * 65536);
    __nv_bfloat16* lo = hi + 128 * 128;
    *(uint32_t*)(hi + kk * 128 + c)     = h0;
    *(uint32_t*)(hi + kk * 128 + c + 2) = h1;
    *(uint32_t*)(lo + kk * 128 + c)     = l0;
    *(uint32_t*)(lo + kk * 128 + c + 2) = l1;
}

// ============================================================================
// K4: typed projections via wmma bf16 split.            [PROFILED SLOT]
// Warp tile 32x64 (2x4 frags); A hi/lo in SMEM (68KB); B frags straight from
// global g_wB (L1-resident, 64KB/set). Outputs bf16 k/q/v rows.
// ============================================================================
__global__ __launch_bounds__(256) void proj_wmma_kernel(
    const float* __restrict__ x, const int* __restrict__ ntype,
    const float* __restrict__ bk, const float* __restrict__ bq,
    const float* __restrict__ bv)
{
    extern __shared__ __align__(16) char dynsm[];
    __nv_bfloat16* Ah = (__nv_bfloat16*)dynsm;
    __nv_bfloat16* Al = Ah + 128 * LDA;
    __shared__ int s_nl[128];
    __shared__ int s_t;
    __shared__ __align__(16) float stg[8][16][24];

    int tid = threadIdx.x, w = tid >> 5, lane = tid & 31;
    if (tid < 128) s_nl[tid] = g_nlist[blockIdx.x * 128 + tid];
    __syncthreads();
    if (tid == 0) {
        int t = -1;
        for (int m = 0; m < 128; m++) if (s_nl[m] >= 0) { t = ntype[s_nl[m]]; break; }
        s_t = t;
    }
    __syncthreads();
    if (s_t < 0) return;

    // stage A: gather x rows, split into bf16 hi/lo
    for (int idx = tid; idx < 128 * 32; idx += 256) {
        int m = idx >> 5, c = (idx & 31) * 4;
        int n = s_nl[m];
        float4 f = (n >= 0) ? *(const float4*)(x + (size_t)n * FDIM + c)
                            : make_float4(0.f, 0.f, 0.f, 0.f);
        uint32_t l0, l1;
        uint32_t h0 = bfsplit(f.x, f.y, l0), h1 = bfsplit(f.z, f.w, l1);
        *(uint32_t*)(Ah + m * LDA + c)     = h0;
        *(uint32_t*)(Ah + m * LDA + c + 2) = h1;
        *(uint32_t*)(Al + m * LDA + c)     = l0;
        *(uint32_t*)(Al + m * LDA + c + 2) = l1;
    }
    __syncthreads();

    int rg = w & 3, cg = w >> 2;           // row group (32 rows), col group (64 cols)
    int row_m = rg * 32;
    int colb = cg * 64;
    int r = lane >> 1, c0 = (lane & 1) * 8;

    for (int set = 0; set < 3; set++) {
        const __nv_bfloat16* GBh = (const __nv_bfloat16*)(g_wB + (size_t)(s_t * 4 + set) * 65536);
        const __nv_bfloat16* GBl = GBh + 128 * 128;

        wmma::fragment<wmma::accumulator, 16, 16, 16, float> acc[2][4];
        #pragma unroll
        for (int mi = 0; mi < 2; mi++)
            #pragma unroll
            for (int ni = 0; ni < 4; ni++) wmma::fill_fragment(acc[mi][ni], 0.f);

        #pragma unroll
        for (int k = 0; k < 8; k++) {
            wmma::fragment<wmma::matrix_a, 16, 16, 16, __nv_bfloat16, wmma::row_major> ah0, ah1, al0, al1;
            wmma::load_matrix_sync(ah0, Ah + (row_m +  0) * LDA + k * 16, LDA);
            wmma::load_matrix_sync(ah1, Ah + (row_m + 16) * LDA + k * 16, LDA);
            wmma::load_matrix_sync(al0, Al + (row_m +  0) * LDA + k * 16, LDA);
            wmma::load_matrix_sync(al1, Al + (row_m + 16) * LDA + k * 16, LDA);
            #pragma unroll
            for (int ni = 0; ni < 4; ni++) {
                wmma::fragment<wmma::matrix_b, 16, 16, 16, __nv_bfloat16, wmma::row_major> bh, bl;
                wmma::load_matrix_sync(bh, GBh + (k * 16) * 128 + colb + ni * 16, 128);
                wmma::load_matrix_sync(bl, GBl + (k * 16) * 128 + colb + ni * 16, 128);
                wmma::mma_sync(acc[0][ni], ah0, bh, acc[0][ni]);
                wmma::mma_sync(acc[0][ni], ah0, bl, acc[0][ni]);
                wmma::mma_sync(acc[0][ni], al0, bh, acc[0][ni]);
                wmma::mma_sync(acc[1][ni], ah1, bh, acc[1][ni]);
                wmma::mma_sync(acc[1][ni], ah1, bl, acc[1][ni]);
                wmma::mma_sync(acc[1][ni], al1, bh, acc[1][ni]);
            }
        }

        __nv_bfloat16* ob = (set == 0) ? g_kb : (set == 1) ? g_qb : g_vb;
        const float* bias = ((set == 0) ? bk : (set == 1) ? bq : bv) + s_t * FDIM;
        #pragma unroll
        for (int mi = 0; mi < 2; mi++) {
            int gr = s_nl[row_m + mi * 16 + r];
            #pragma unroll
            for (int ni = 0; ni < 4; ni++) {
                wmma::store_matrix_sync(&stg[w][0][0], acc[mi][ni], 24, wmma::mem_row_major);
                __syncwarp();
                if (gr >= 0) {
                    int col = colb + ni * 16 + c0;
                    float4 v0 = *(float4*)&stg[w][r][c0];
                    float4 v1 = *(float4*)&stg[w][r][c0 + 4];
                    v0.x += bias[col + 0]; v0.y += bias[col + 1];
                    v0.z += bias[col + 2]; v0.w += bias[col + 3];
                    v1.x += bias[col + 4]; v1.y += bias[col + 5];
                    v1.z += bias[col + 6]; v1.w += bias[col + 7];
                    __nv_bfloat162 p0 = __floats2bfloat162_rn(v0.x, v0.y);
                    __nv_bfloat162 p1 = __floats2bfloat162_rn(v0.z, v0.w);
                    __nv_bfloat162 p2 = __floats2bfloat162_rn(v1.x, v1.y);
                    __nv_bfloat162 p3 = __floats2bfloat162_rn(v1.z, v1.w);
                    uint4 pk = make_uint4(*(uint32_t*)&p0, *(uint32_t*)&p1,
                                          *(uint32_t*)&p2, *(uint32_t*)&p3);
                    *(uint4*)(ob + (size_t)gr * FDIM + col) = pk;
                }
                __syncwarp();
            }
        }
    }
}

// ============================================================================
// K5: zero accumulators (g_acc, g_den)
// ============================================================================
__global__ void zero_kernel() {
    int stride = gridDim.x * blockDim.x;
    for (int idx = blockIdx.x * blockDim.x + threadIdx.x; idx < NMAX * FDIM; idx += stride) {
        g_acc[idx] = 0.f;
        if (idx < NRH) g_den[idx] = 0.f;
    }
}

// ============================================================================
// K6: edge scores + exp + segment denom. k/q gathered as bf16 (half traffic).
// Warp per edge. lane = h*4 + q. SMEM matrices padded -> conflict-free.
// ============================================================================
#define MATPAD 272
__global__ __launch_bounds__(256) void score_kernel(
    const int* __restrict__ src, const int* __restrict__ dst,
    const int* __restrict__ etype,
    const float* __restrict__ rel_pri, const float* __restrict__ rel_att, int E) {
    __shared__ __align__(16) float s_att[RR * HH * MATPAD];
    __shared__ float s_pri[RR * HH];
    for (int idx = threadIdx.x; idx < RR * HH * DKK * DKK; idx += 256) {
        int mat = idx >> 8, inner = idx & 255;
        s_att[mat * MATPAD + inner] = rel_att[idx];
    }
    if (threadIdx.x < RR * HH) s_pri[threadIdx.x] = rel_pri[threadIdx.x];
    __syncthreads();

    int warp = threadIdx.x >> 5;
    int lane = threadIdx.x & 31;
    int h = lane >> 2, qq = lane & 3;
    for (int e = blockIdx.x * 8 + warp; e < E; e += gridDim.x * 8) {
        int s = src[e], d = dst[e], r = etype[e];
        // k row of head h: 16 bf16 = 32B (broadcast across the 4 lanes of a head)
        const uint4* kp = (const uint4*)(g_kb + (size_t)s * FDIM + h * DKK);
        uint4 ku0 = kp[0], ku1 = kp[1];
        float kr[16];
        {
            float2 f;
            f = bf2f2(ku0.x); kr[0]=f.x; kr[1]=f.y;
            f = bf2f2(ku0.y); kr[2]=f.x; kr[3]=f.y;
            f = bf2f2(ku0.z); kr[4]=f.x; kr[5]=f.y;
            f = bf2f2(ku0.w); kr[6]=f.x; kr[7]=f.y;
            f = bf2f2(ku1.x); kr[8]=f.x; kr[9]=f.y;
            f = bf2f2(ku1.y); kr[10]=f.x; kr[11]=f.y;
            f = bf2f2(ku1.z); kr[12]=f.x; kr[13]=f.y;
            f = bf2f2(ku1.w); kr[14]=f.x; kr[15]=f.y;
        }
        // q quad for this lane: 4 bf16 = 8B
        uint2 qu = *(const uint2*)(g_qb + (size_t)d * FDIM + h * DKK + qq * 4);
        float2 q01 = bf2f2(qu.x), q23 = bf2f2(qu.y);
        const float* A = s_att + (r * HH + h) * MATPAD + qq * 4;
        float4 t = make_float4(0.f, 0.f, 0.f, 0.f);
        #pragma unroll
        for (int dd = 0; dd < 16; dd++) {
            float4 av = *(const float4*)(A + dd * DKK);
            float kc = kr[dd];
            t.x = fmaf(kc, av.x, t.x);
            t.y = fmaf(kc, av.y, t.y);
            t.z = fmaf(kc, av.z, t.z);
            t.w = fmaf(kc, av.w, t.w);
        }
        float sc = t.x*q01.x + t.y*q01.y + t.z*q23.x + t.w*q23.y;
        sc += __shfl_xor_sync(0xFFFFFFFFu, sc, 1);
        sc += __shfl_xor_sync(0xFFFFFFFFu, sc, 2);
        sc *= s_pri[r * HH + h] * (1.0f / SQRT_DK);
        if (qq == 0) {
            float p = __expf(sc);
            g_a[e * HH + h] = p;
            atomicAdd(&g_den[(d * RR + r) * HH + h], p);
        }
    }
}

// ============================================================================
// K7: weighted message aggregation. v gathered as bf16.
// ============================================================================
__global__ __launch_bounds__(256) void agg_kernel(
    const int* __restrict__ src, const int* __restrict__ dst,
    const int* __restrict__ etype, const float* __restrict__ rel_msg, int E) {
    __shared__ __align__(16) float s_msg[RR * HH * MATPAD];
    for (int idx = threadIdx.x; idx < RR * HH * DKK * DKK; idx += 256) {
        int mat = idx >> 8, inner = idx & 255;
        s_msg[mat * MATPAD + inner] = rel_msg[idx];
    }
    __syncthreads();

    int warp = threadIdx.x >> 5;
    int lane = threadIdx.x & 31;
    int h = lane >> 2, qq = lane & 3;
    for (int e = blockIdx.x * 8 + warp; e < E; e += gridDim.x * 8) {
        int s = src[e], d = dst[e], r = etype[e];
        float p = g_a[e * HH + h];
        float den = g_den[(d * RR + r) * HH + h];
        float attw = p / den;
        const uint4* vp = (const uint4*)(g_vb + (size_t)s * FDIM + h * DKK);
        uint4 vu0 = vp[0], vu1 = vp[1];
        float vr[16];
        {
            float2 f;
            f = bf2f2(vu0.x); vr[0]=f.x; vr[1]=f.y;
            f = bf2f2(vu0.y); vr[2]=f.x; vr[3]=f.y;
            f = bf2f2(vu0.z); vr[4]=f.x; vr[5]=f.y;
            f = bf2f2(vu0.w); vr[6]=f.x; vr[7]=f.y;
            f = bf2f2(vu1.x); vr[8]=f.x; vr[9]=f.y;
            f = bf2f2(vu1.y); vr[10]=f.x; vr[11]=f.y;
            f = bf2f2(vu1.z); vr[12]=f.x; vr[13]=f.y;
            f = bf2f2(vu1.w); vr[14]=f.x; vr[15]=f.y;
        }
        const float* M = s_msg + (r * HH + h) * MATPAD + qq * 4;
        float4 o = make_float4(0.f, 0.f, 0.f, 0.f);
        #pragma unroll
        for (int dd = 0; dd < 16; dd++) {
            float4 mv = *(const float4*)(M + dd * DKK);
            float vc = vr[dd];
            o.x = fmaf(vc, mv.x, o.x);
            o.y = fmaf(vc, mv.y, o.y);
            o.z = fmaf(vc, mv.z, o.z);
            o.w = fmaf(vc, mv.w, o.w);
        }
        float4 add = make_float4(attw*o.x, attw*o.y, attw*o.z, attw*o.w);
        atomicAdd((float4*)(g_acc + d * FDIM + h * DKK + qq * 4), add);
    }
}

// ============================================================================
// K8: mean-over-etypes, Wa proj (wmma split-bf16), skip blend, per-type LN
// ============================================================================
__global__ __launch_bounds__(256) void final_wmma_kernel(
    const float* __restrict__ x, const int* __restrict__ ntype,
    const float* __restrict__ ba, const float* __restrict__ skipv,
    const float* __restrict__ ln_g, const float* __restrict__ ln_b,
    float* __restrict__ out)
{
    extern __shared__ __align__(16) char dynsm[];
    __nv_bfloat16* Ah = (__nv_bfloat16*)dynsm;
    __nv_bfloat16* Al = Ah + 128 * LDA;
    float* F = (float*)dynsm;                 // fp32 tile [128][FLD]; aliased AFTER GEMM
    __shared__ int s_nl[128];
    __shared__ int s_t;
    __shared__ float s_scp[128];

    int tid = threadIdx.x, w = tid >> 5, lane = tid & 31;
    if (tid < 128) s_nl[tid] = g_nlist[blockIdx.x * 128 + tid];
    __syncthreads();
    if (tid == 0) {
        int t = -1;
        for (int m = 0; m < 128; m++) if (s_nl[m] >= 0) { t = ntype[s_nl[m]]; break; }
        s_t = t;
    }
    if (tid < 128) {
        int n = s_nl[tid];
        float inv = 1.f;
        if (n >= 0) {
            int cp = 0;
            for (int r = 0; r < RR; r++) cp += (g_den[(n * RR + r) * HH] > 0.f) ? 1 : 0;
            if (cp < 1) cp = 1;
            inv = 1.f / (float)cp;
        }
        s_scp[tid] = inv;
    }
    __syncthreads();
    if (s_t < 0) return;

    // stage A: T = g_acc * scp, split bf16 hi/lo
    for (int idx = tid; idx < 128 * 32; idx += 256) {
        int m = idx >> 5, c = (idx & 31) * 4;
        int n = s_nl[m];
        float4 f = make_float4(0.f, 0.f, 0.f, 0.f);
        if (n >= 0) {
            f = *(const float4*)(g_acc + (size_t)n * FDIM + c);
            float sc = s_scp[m];
            f.x *= sc; f.y *= sc; f.z *= sc; f.w *= sc;
        }
        uint32_t l0, l1;
        uint32_t h0 = bfsplit(f.x, f.y, l0), h1 = bfsplit(f.z, f.w, l1);
        *(uint32_t*)(Ah + m * LDA + c)     = h0;
        *(uint32_t*)(Ah + m * LDA + c + 2) = h1;
        *(uint32_t*)(Al + m * LDA + c)     = l0;
        *(uint32_t*)(Al + m * LDA + c + 2) = l1;
    }
    __syncthreads();

    int rg = w & 3, cg = w >> 2;
    int row_m = rg * 32;
    int colb = cg * 64;
    const __nv_bfloat16* GBh = (const __nv_bfloat16*)(g_wB + (size_t)(s_t * 4 + 3) * 65536);
    const __nv_bfloat16* GBl = GBh + 128 * 128;

    wmma::fragment<wmma::accumulator, 16, 16, 16, float> acc[2][4];
    #pragma unroll
    for (int mi = 0; mi < 2; mi++)
        #pragma unroll
        for (int ni = 0; ni < 4; ni++) wmma::fill_fragment(acc[mi][ni], 0.f);

    #pragma unroll
    for (int k = 0; k < 8; k++) {
        wmma::fragment<wmma::matrix_a, 16, 16, 16, __nv_bfloat16, wmma::row_major> ah0, ah1, al0, al1;
        wmma::load_matrix_sync(ah0, Ah + (row_m +  0) * LDA + k * 16, LDA);
        wmma::load_matrix_sync(ah1, Ah + (row_m + 16) * LDA + k * 16, LDA);
        wmma::load_matrix_sync(al0, Al + (row_m +  0) * LDA + k * 16, LDA);
        wmma::load_matrix_sync(al1, Al + (row_m + 16) * LDA + k * 16, LDA);
        #pragma unroll
        for (int ni = 0; ni < 4; ni++) {
            wmma::fragment<wmma::matrix_b, 16, 16, 16, __nv_bfloat16, wmma::row_major> bh, bl;
            wmma::load_matrix_sync(bh, GBh + (k * 16) * 128 + colb + ni * 16, 128);
            wmma::load_matrix_sync(bl, GBl + (k * 16) * 128 + colb + ni * 16, 128);
            wmma::mma_sync(acc[0][ni], ah0, bh, acc[0][ni]);
            wmma::mma_sync(acc[0][ni], ah0, bl, acc[0][ni]);
            wmma::mma_sync(acc[0][ni], al0, bh, acc[0][ni]);
            wmma::mma_sync(acc[1][ni], ah1, bh, acc[1][ni]);
            wmma::mma_sync(acc[1][ni], ah1, bl, acc[1][ni]);
            wmma::mma_sync(acc[1][ni], al1, bh, acc[1][ni]);
        }
    }
    __syncthreads();   // all bf16 stage reads done; F may alias

    #pragma unroll
    for (int mi = 0; mi < 2; mi++)
        #pragma unroll
        for (int ni = 0; ni < 4; ni++)
            wmma::store_matrix_sync(F + (row_m + mi * 16) * FLD + colb + ni * 16,
                                    acc[mi][ni], FLD, wmma::mem_row_major);
    __syncthreads();

    // epilogue: skip blend + per-type LN; warp w handles rows w*16..w*16+15
    float alpha = 1.f / (1.f + __expf(-skipv[s_t]));
    float beta = 1.f - alpha;
    int c0 = lane * 4;
    float4 bav = *(const float4*)(ba   + s_t * FDIM + c0);
    float4 gv  = *(const float4*)(ln_g + s_t * FDIM + c0);
    float4 bv2 = *(const float4*)(ln_b + s_t * FDIM + c0);
    int rbase = w * 16;
    for (int q = 0; q < 16; q++) {
        int m = rbase + q;
        int n = s_nl[m];
        if (n < 0) continue;
        float4 tr = *(float4*)(F + m * FLD + c0);
        float4 xv = *(const float4*)(x + (size_t)n * FDIM + c0);
        float4 v;
        v.x = (tr.x + bav.x) * alpha + xv.x * beta;
        v.y = (tr.y + bav.y) * alpha + xv.y * beta;
        v.z = (tr.z + bav.z) * alpha + xv.z * beta;
        v.w = (tr.w + bav.w) * alpha + xv.w * beta;
        float s  = v.x + v.y + v.z + v.w;
        float s2 = v.x*v.x + v.y*v.y + v.z*v.z + v.w*v.w;
        #pragma unroll
        for (int o = 16; o; o >>= 1) {
            s  += __shfl_xor_sync(0xFFFFFFFFu, s,  o);
            s2 += __shfl_xor_sync(0xFFFFFFFFu, s2, o);
        }
        float mu = s * (1.f / 128.f);
        float var = s2 * (1.f / 128.f) - mu * mu;
        float rstd = rsqrtf(var + 1e-5f);
        float4 ov;
        ov.x = (v.x - mu) * rstd * gv.x + bv2.x;
        ov.y = (v.y - mu) * rstd * gv.y + bv2.y;
        ov.z = (v.z - mu) * rstd * gv.z + bv2.z;
        ov.w = (v.w - mu) * rstd * gv.w + bv2.w;
        *(float4*)(out + (size_t)n * FDIM + c0) = ov;
    }
}

// ---------------- launch ----------------
extern "C" void kernel_launch(void* const* d_in, const int* in_sizes, int n_in,
                              void* d_out, int out_size) {
    const float* x       = (const float*)d_in[0];
    const int*   ntype   = (const int*)  d_in[1];
    const int*   src     = (const int*)  d_in[2];
    const int*   dst     = (const int*)  d_in[3];
    const int*   etype   = (const int*)  d_in[4];
    const float* Wk      = (const float*)d_in[5];
    const float* bk      = (const float*)d_in[6];
    const float* Wq      = (const float*)d_in[7];
    const float* bq      = (const float*)d_in[8];
    const float* Wv      = (const float*)d_in[9];
    const float* bv      = (const float*)d_in[10];
    const float* Wa      = (const float*)d_in[11];
    const float* ba      = (const float*)d_in[12];
    const float* rel_pri = (const float*)d_in[13];
    const float* rel_att = (const float*)d_in[14];
    const float* rel_msg = (const float*)d_in[15];
    const float* skipv   = (const float*)d_in[16];
    const float* ln_g    = (const float*)d_in[17];
    const float* ln_b    = (const float*)d_in[18];
    float* out = (float*)d_out;

    const int N = in_sizes[1];
    const int E = in_sizes[2];
    const int A_SMEM = 2 * 128 * LDA * 2;              // 69632 B (Ah|Al)
    const int F_SMEM = 128 * FLD * 4;                  // 67584 B (fp32 tile)
    const int FIN_SMEM = (A_SMEM > F_SMEM) ? A_SMEM : F_SMEM;

    cudaFuncSetAttribute(proj_wmma_kernel,  cudaFuncAttributeMaxDynamicSharedMemorySize, A_SMEM);
    cudaFuncSetAttribute(final_wmma_kernel, cudaFuncAttributeMaxDynamicSharedMemorySize, FIN_SMEM);

    prep_kernel<<<1, 1024>>>(ntype, N);
    scatter_kernel<<<(N + 255) / 256, 256>>>(ntype, N);
    wconv_kernel<<<(TT * 4 * 128 * 32 + 255) / 256, 256>>>(Wk, Wq, Wv, Wa);
    proj_wmma_kernel<<<NL_CAP / 128, 256, A_SMEM>>>(x, ntype, bk, bq, bv);   // profiled slot
    zero_kernel<<<4096, 256>>>();
    score_kernel<<<2048, 256>>>(src, dst, etype, rel_pri, rel_att, E);
    agg_kernel<<<2048, 256>>>(src, dst, etype, rel_msg, E);
    final_wmma_kernel<<<NL_CAP / 128, 256, FIN_SMEM>>>(x, ntype, ba, skipv, ln_g, ln_b, out);
}

// round 9
// speedup vs baseline: 1.3122x; 1.1150x over previous
#include <cuda_runtime.h>
#include <cuda_bf16.h>
#include <mma.h>
#include <stdint.h>
#include <math.h>

using namespace nvcuda;

// Problem constants (AttentionLayer_11776800325798)
#define NMAX   50000
#define EMAX   500000
#define TT     3
#define RR     5
#define HH     8
#define DKK    16
#define FDIM   128
#define NRH    (NMAX * RR * HH)                      // 2,000,000
#define NL_CAP (((NMAX / 128) + TT + 1) * 128)       // 50432, 128-padded per type
#define SQRT_DK 4.0f
#define LDA 136                                      // bf16 elems per row (128 + 8 pad)
#define FLD 132                                      // fp32 staging tile stride

// ---------------- scratch (static __device__, no allocation) ----------------
__device__ __nv_bfloat16 g_kb[NMAX * FDIM];
__device__ __nv_bfloat16 g_qb[NMAX * FDIM];
__device__ __nv_bfloat16 g_vb[NMAX * FDIM];
__device__ float    g_acc[NMAX * FDIM];
__device__ float    g_a[EMAX * HH];
__device__ float    g_den[NRH];
__device__ int      g_nlist[NL_CAP];
__device__ int      g_cur[TT];
__device__ int      g_poff[TT + 1];
// pre-converted weights: [type][set(k,q,v,a)][hi|lo] each 128x128 bf16 row-major (32KB)
__device__ __align__(16) unsigned char g_wB[TT * 4 * 2 * 32768];

// fp32 -> bf16 hi + bf16 lo (packed pairs)
__device__ __forceinline__ uint32_t bfsplit(float a, float b, uint32_t& lo) {
    __nv_bfloat162 h = __floats2bfloat162_rn(a, b);
    float ra = a - __bfloat162float(h.x);
    float rb = b - __bfloat162float(h.y);
    __nv_bfloat162 l = __floats2bfloat162_rn(ra, rb);
    lo = *reinterpret_cast<uint32_t*>(&l);
    return *reinterpret_cast<uint32_t*>(&h);
}
__device__ __forceinline__ float2 bf2f2(uint32_t u) {
    __nv_bfloat162 b = *reinterpret_cast<__nv_bfloat162*>(&u);
    return __bfloat1622float2(b);
}

// ============================================================================
// K1: prep — fused counter zero + type histogram + scan + nlist init (1 block)
// ============================================================================
__global__ __launch_bounds__(1024) void prep_kernel(const int* __restrict__ ntype, int N) {
    __shared__ int scnt[TT];
    int tid = threadIdx.x;
    if (tid < TT) scnt[tid] = 0;
    __syncthreads();
    int c0 = 0, c1 = 0, c2 = 0;
    for (int i = tid; i < N; i += 1024) {
        int t = ntype[i];
        c0 += (t == 0); c1 += (t == 1); c2 += (t == 2);
    }
    if (c0) atomicAdd(&scnt[0], c0);
    if (c1) atomicAdd(&scnt[1], c1);
    if (c2) atomicAdd(&scnt[2], c2);
    __syncthreads();
    if (tid == 0) {
        int o = 0;
        for (int t = 0; t < TT; t++) { g_poff[t] = o; o += ((scnt[t] + 127) / 128) * 128; }
        g_poff[TT] = o;
    }
    if (tid < TT) g_cur[tid] = 0;
    for (int i = tid; i < NL_CAP; i += 1024) g_nlist[i] = -1;
}

// ============================================================================
// K2: scatter nodes into type-sorted, 128-padded list (warp-aggregated)
// ============================================================================
__global__ void scatter_kernel(const int* __restrict__ ntype, int N) {
    int i = blockIdx.x * blockDim.x + threadIdx.x;
    int t = (i < N) ? ntype[i] : -1;
    #pragma unroll
    for (int tt = 0; tt < TT; tt++) {
        unsigned mask = __ballot_sync(0xFFFFFFFFu, t == tt);
        if (t == tt) {
            int lane = threadIdx.x & 31;
            int leader = __ffs(mask) - 1;
            int rank = __popc(mask & ((1u << lane) - 1));
            int base = 0;
            if (lane == leader) base = atomicAdd(&g_cur[tt], __popc(mask));
            base = __shfl_sync(mask, base, leader);
            g_nlist[g_poff[tt] + base + rank] = i;
        }
    }
}

// ============================================================================
// K3: weight pre-conversion: all 4 W sets -> bf16 hi/lo row-major [128][128]
// ============================================================================
__global__ void wconv_kernel(const float* __restrict__ Wk, const float* __restrict__ Wq,
                             const float* __restrict__ Wv, const float* __restrict__ Wa) {
    int idx = blockIdx.x * blockDim.x + threadIdx.x;
    if (idx >= TT * 4 * 128 * 32) return;
    int c = (idx & 31) * 4;
    int kk = (idx >> 5) & 127;
    int g = idx >> 12;                             // 0..11 = t*4+set
    int set = g & 3, t = g >> 2;
    const float* W = ((set == 0) ? Wk : (set == 1) ? Wq : (set == 2) ? Wv : Wa) + t * FDIM * FDIM;
    float4 f = *(const float4*)(W + kk * FDIM + c);
    uint32_t l0, l1;
    uint32_t h0 = bfsplit(f.x, f.y, l0), h1 = bfsplit(f.z, f.w, l1);
    __nv_bfloat16* hi = (__nv_bfloat16*)(g_wB + (size_t)g * 65536);
    __nv_bfloat16* lo = hi + 128 * 128;
    *(uint32_t*)(hi + kk * 128 + c)     = h0;
    *(uint32_t*)(hi + kk * 128 + c + 2) = h1;
    *(uint32_t*)(lo + kk * 128 + c)     = l0;
    *(uint32_t*)(lo + kk * 128 + c + 2) = l1;
}

// ============================================================================
// K4: typed projections via wmma PLAIN bf16 (outputs are bf16 anyway).
// Warp tile 32x64; A(hi) in SMEM 34KB; B(hi) frags from global (L1-resident).
// regs ~105 + launch_bounds(256,2) -> 2 CTAs/SM.          [PROFILED SLOT]
// ============================================================================
__global__ __launch_bounds__(256, 2) void proj_wmma_kernel(
    const float* __restrict__ x, const int* __restrict__ ntype,
    const float* __restrict__ bk, const float* __restrict__ bq,
    const float* __restrict__ bv)
{
    extern __shared__ __align__(16) char dynsm[];
    __nv_bfloat16* Ah = (__nv_bfloat16*)dynsm;
    __shared__ int s_nl[128];
    __shared__ int s_t;
    __shared__ __align__(16) float stg[8][16][24];

    int tid = threadIdx.x, w = tid >> 5, lane = tid & 31;
    if (tid < 128) s_nl[tid] = g_nlist[blockIdx.x * 128 + tid];
    __syncthreads();
    if (tid == 0) {
        int t = -1;
        for (int m = 0; m < 128; m++) if (s_nl[m] >= 0) { t = ntype[s_nl[m]]; break; }
        s_t = t;
    }
    __syncthreads();
    if (s_t < 0) return;

    // stage A: gather x rows -> bf16
    for (int idx = tid; idx < 128 * 32; idx += 256) {
        int m = idx >> 5, c = (idx & 31) * 4;
        int n = s_nl[m];
        float4 f = (n >= 0) ? *(const float4*)(x + (size_t)n * FDIM + c)
                            : make_float4(0.f, 0.f, 0.f, 0.f);
        __nv_bfloat162 p0 = __floats2bfloat162_rn(f.x, f.y);
        __nv_bfloat162 p1 = __floats2bfloat162_rn(f.z, f.w);
        *(uint32_t*)(Ah + m * LDA + c)     = *(uint32_t*)&p0;
        *(uint32_t*)(Ah + m * LDA + c + 2) = *(uint32_t*)&p1;
    }
    __syncthreads();

    int rg = w & 3, cg = w >> 2;           // row group (32 rows), col group (64 cols)
    int row_m = rg * 32;
    int colb = cg * 64;
    int r = lane >> 1, c0 = (lane & 1) * 8;

    for (int set = 0; set < 3; set++) {
        const __nv_bfloat16* GBh = (const __nv_bfloat16*)(g_wB + (size_t)(s_t * 4 + set) * 65536);

        wmma::fragment<wmma::accumulator, 16, 16, 16, float> acc[2][4];
        #pragma unroll
        for (int mi = 0; mi < 2; mi++)
            #pragma unroll
            for (int ni = 0; ni < 4; ni++) wmma::fill_fragment(acc[mi][ni], 0.f);

        #pragma unroll
        for (int k = 0; k < 8; k++) {
            wmma::fragment<wmma::matrix_a, 16, 16, 16, __nv_bfloat16, wmma::row_major> ah0, ah1;
            wmma::load_matrix_sync(ah0, Ah + (row_m +  0) * LDA + k * 16, LDA);
            wmma::load_matrix_sync(ah1, Ah + (row_m + 16) * LDA + k * 16, LDA);
            #pragma unroll
            for (int ni = 0; ni < 4; ni++) {
                wmma::fragment<wmma::matrix_b, 16, 16, 16, __nv_bfloat16, wmma::row_major> bh;
                wmma::load_matrix_sync(bh, GBh + (k * 16) * 128 + colb + ni * 16, 128);
                wmma::mma_sync(acc[0][ni], ah0, bh, acc[0][ni]);
                wmma::mma_sync(acc[1][ni], ah1, bh, acc[1][ni]);
            }
        }

        __nv_bfloat16* ob = (set == 0) ? g_kb : (set == 1) ? g_qb : g_vb;
        const float* bias = ((set == 0) ? bk : (set == 1) ? bq : bv) + s_t * FDIM;
        #pragma unroll
        for (int mi = 0; mi < 2; mi++) {
            int gr = s_nl[row_m + mi * 16 + r];
            #pragma unroll
            for (int ni = 0; ni < 4; ni++) {
                wmma::store_matrix_sync(&stg[w][0][0], acc[mi][ni], 24, wmma::mem_row_major);
                __syncwarp();
                if (gr >= 0) {
                    int col = colb + ni * 16 + c0;
                    float4 v0 = *(float4*)&stg[w][r][c0];
                    float4 v1 = *(float4*)&stg[w][r][c0 + 4];
                    v0.x += bias[col + 0]; v0.y += bias[col + 1];
                    v0.z += bias[col + 2]; v0.w += bias[col + 3];
                    v1.x += bias[col + 4]; v1.y += bias[col + 5];
                    v1.z += bias[col + 6]; v1.w += bias[col + 7];
                    __nv_bfloat162 p0 = __floats2bfloat162_rn(v0.x, v0.y);
                    __nv_bfloat162 p1 = __floats2bfloat162_rn(v0.z, v0.w);
                    __nv_bfloat162 p2 = __floats2bfloat162_rn(v1.x, v1.y);
                    __nv_bfloat162 p3 = __floats2bfloat162_rn(v1.z, v1.w);
                    uint4 pk = make_uint4(*(uint32_t*)&p0, *(uint32_t*)&p1,
                                          *(uint32_t*)&p2, *(uint32_t*)&p3);
                    *(uint4*)(ob + (size_t)gr * FDIM + col) = pk;
                }
                __syncwarp();
            }
        }
    }
}

// ============================================================================
// K5: zero accumulators (g_acc, g_den)
// ============================================================================
__global__ void zero_kernel() {
    int stride = gridDim.x * blockDim.x;
    for (int idx = blockIdx.x * blockDim.x + threadIdx.x; idx < NMAX * FDIM; idx += stride) {
        g_acc[idx] = 0.f;
        if (idx < NRH) g_den[idx] = 0.f;
    }
}

// ============================================================================
// K6: edge scores + exp + segment denom. k/q gathered as bf16.
// ============================================================================
#define MATPAD 272
__global__ __launch_bounds__(256) void score_kernel(
    const int* __restrict__ src, const int* __restrict__ dst,
    const int* __restrict__ etype,
    const float* __restrict__ rel_pri, const float* __restrict__ rel_att, int E) {
    __shared__ __align__(16) float s_att[RR * HH * MATPAD];
    __shared__ float s_pri[RR * HH];
    for (int idx = threadIdx.x; idx < RR * HH * DKK * DKK; idx += 256) {
        int mat = idx >> 8, inner = idx & 255;
        s_att[mat * MATPAD + inner] = rel_att[idx];
    }
    if (threadIdx.x < RR * HH) s_pri[threadIdx.x] = rel_pri[threadIdx.x];
    __syncthreads();

    int warp = threadIdx.x >> 5;
    int lane = threadIdx.x & 31;
    int h = lane >> 2, qq = lane & 3;
    for (int e = blockIdx.x * 8 + warp; e < E; e += gridDim.x * 8) {
        int s = src[e], d = dst[e], r = etype[e];
        const uint4* kp = (const uint4*)(g_kb + (size_t)s * FDIM + h * DKK);
        uint4 ku0 = kp[0], ku1 = kp[1];
        float kr[16];
        {
            float2 f;
            f = bf2f2(ku0.x); kr[0]=f.x; kr[1]=f.y;
            f = bf2f2(ku0.y); kr[2]=f.x; kr[3]=f.y;
            f = bf2f2(ku0.z); kr[4]=f.x; kr[5]=f.y;
            f = bf2f2(ku0.w); kr[6]=f.x; kr[7]=f.y;
            f = bf2f2(ku1.x); kr[8]=f.x; kr[9]=f.y;
            f = bf2f2(ku1.y); kr[10]=f.x; kr[11]=f.y;
            f = bf2f2(ku1.z); kr[12]=f.x; kr[13]=f.y;
            f = bf2f2(ku1.w); kr[14]=f.x; kr[15]=f.y;
        }
        uint2 qu = *(const uint2*)(g_qb + (size_t)d * FDIM + h * DKK + qq * 4);
        float2 q01 = bf2f2(qu.x), q23 = bf2f2(qu.y);
        const float* A = s_att + (r * HH + h) * MATPAD + qq * 4;
        float4 t = make_float4(0.f, 0.f, 0.f, 0.f);
        #pragma unroll
        for (int dd = 0; dd < 16; dd++) {
            float4 av = *(const float4*)(A + dd * DKK);
            float kc = kr[dd];
            t.x = fmaf(kc, av.x, t.x);
            t.y = fmaf(kc, av.y, t.y);
            t.z = fmaf(kc, av.z, t.z);
            t.w = fmaf(kc, av.w, t.w);
        }
        float sc = t.x*q01.x + t.y*q01.y + t.z*q23.x + t.w*q23.y;
        sc += __shfl_xor_sync(0xFFFFFFFFu, sc, 1);
        sc += __shfl_xor_sync(0xFFFFFFFFu, sc, 2);
        sc *= s_pri[r * HH + h] * (1.0f / SQRT_DK);
        if (qq == 0) {
            float p = __expf(sc);
            g_a[e * HH + h] = p;
            atomicAdd(&g_den[(d * RR + r) * HH + h], p);
        }
    }
}

// ============================================================================
// K7: weighted message aggregation. v gathered as bf16.
// ============================================================================
__global__ __launch_bounds__(256) void agg_kernel(
    const int* __restrict__ src, const int* __restrict__ dst,
    const int* __restrict__ etype, const float* __restrict__ rel_msg, int E) {
    __shared__ __align__(16) float s_msg[RR * HH * MATPAD];
    for (int idx = threadIdx.x; idx < RR * HH * DKK * DKK; idx += 256) {
        int mat = idx >> 8, inner = idx & 255;
        s_msg[mat * MATPAD + inner] = rel_msg[idx];
    }
    __syncthreads();

    int warp = threadIdx.x >> 5;
    int lane = threadIdx.x & 31;
    int h = lane >> 2, qq = lane & 3;
    for (int e = blockIdx.x * 8 + warp; e < E; e += gridDim.x * 8) {
        int s = src[e], d = dst[e], r = etype[e];
        float p = g_a[e * HH + h];
        float den = g_den[(d * RR + r) * HH + h];
        float attw = p / den;
        const uint4* vp = (const uint4*)(g_vb + (size_t)s * FDIM + h * DKK);
        uint4 vu0 = vp[0], vu1 = vp[1];
        float vr[16];
        {
            float2 f;
            f = bf2f2(vu0.x); vr[0]=f.x; vr[1]=f.y;
            f = bf2f2(vu0.y); vr[2]=f.x; vr[3]=f.y;
            f = bf2f2(vu0.z); vr[4]=f.x; vr[5]=f.y;
            f = bf2f2(vu0.w); vr[6]=f.x; vr[7]=f.y;
            f = bf2f2(vu1.x); vr[8]=f.x; vr[9]=f.y;
            f = bf2f2(vu1.y); vr[10]=f.x; vr[11]=f.y;
            f = bf2f2(vu1.z); vr[12]=f.x; vr[13]=f.y;
            f = bf2f2(vu1.w); vr[14]=f.x; vr[15]=f.y;
        }
        const float* M = s_msg + (r * HH + h) * MATPAD + qq * 4;
        float4 o = make_float4(0.f, 0.f, 0.f, 0.f);
        #pragma unroll
        for (int dd = 0; dd < 16; dd++) {
            float4 mv = *(const float4*)(M + dd * DKK);
            float vc = vr[dd];
            o.x = fmaf(vc, mv.x, o.x);
            o.y = fmaf(vc, mv.y, o.y);
            o.z = fmaf(vc, mv.z, o.z);
            o.w = fmaf(vc, mv.w, o.w);
        }
        float4 add = make_float4(attw*o.x, attw*o.y, attw*o.z, attw*o.w);
        atomicAdd((float4*)(g_acc + d * FDIM + h * DKK + qq * 4), add);
    }
}

// ============================================================================
// K8: mean-over-etypes, Wa proj (wmma split-bf16), skip blend, per-type LN
// ============================================================================
__global__ __launch_bounds__(256) void final_wmma_kernel(
    const float* __restrict__ x, const int* __restrict__ ntype,
    const float* __restrict__ ba, const float* __restrict__ skipv,
    const float* __restrict__ ln_g, const float* __restrict__ ln_b,
    float* __restrict__ out)
{
    extern __shared__ __align__(16) char dynsm[];
    __nv_bfloat16* Ah = (__nv_bfloat16*)dynsm;
    __nv_bfloat16* Al = Ah + 128 * LDA;
    float* F = (float*)dynsm;                 // fp32 tile [128][FLD]; aliased AFTER GEMM
    __shared__ int s_nl[128];
    __shared__ int s_t;
    __shared__ float s_scp[128];

    int tid = threadIdx.x, w = tid >> 5, lane = tid & 31;
    if (tid < 128) s_nl[tid] = g_nlist[blockIdx.x * 128 + tid];
    __syncthreads();
    if (tid == 0) {
        int t = -1;
        for (int m = 0; m < 128; m++) if (s_nl[m] >= 0) { t = ntype[s_nl[m]]; break; }
        s_t = t;
    }
    if (tid < 128) {
        int n = s_nl[tid];
        float inv = 1.f;
        if (n >= 0) {
            int cp = 0;
            for (int r = 0; r < RR; r++) cp += (g_den[(n * RR + r) * HH] > 0.f) ? 1 : 0;
            if (cp < 1) cp = 1;
            inv = 1.f / (float)cp;
        }
        s_scp[tid] = inv;
    }
    __syncthreads();
    if (s_t < 0) return;

    // stage A: T = g_acc * scp, split bf16 hi/lo
    for (int idx = tid; idx < 128 * 32; idx += 256) {
        int m = idx >> 5, c = (idx & 31) * 4;
        int n = s_nl[m];
        float4 f = make_float4(0.f, 0.f, 0.f, 0.f);
        if (n >= 0) {
            f = *(const float4*)(g_acc + (size_t)n * FDIM + c);
            float sc = s_scp[m];
            f.x *= sc; f.y *= sc; f.z *= sc; f.w *= sc;
        }
        uint32_t l0, l1;
        uint32_t h0 = bfsplit(f.x, f.y, l0), h1 = bfsplit(f.z, f.w, l1);
        *(uint32_t*)(Ah + m * LDA + c)     = h0;
        *(uint32_t*)(Ah + m * LDA + c + 2) = h1;
        *(uint32_t*)(Al + m * LDA + c)     = l0;
        *(uint32_t*)(Al + m * LDA + c + 2) = l1;
    }
    __syncthreads();

    int rg = w & 3, cg = w >> 2;
    int row_m = rg * 32;
    int colb = cg * 64;
    const __nv_bfloat16* GBh = (const __nv_bfloat16*)(g_wB + (size_t)(s_t * 4 + 3) * 65536);
    const __nv_bfloat16* GBl = GBh + 128 * 128;

    wmma::fragment<wmma::accumulator, 16, 16, 16, float> acc[2][4];
    #pragma unroll
    for (int mi = 0; mi < 2; mi++)
        #pragma unroll
        for (int ni = 0; ni < 4; ni++) wmma::fill_fragment(acc[mi][ni], 0.f);

    #pragma unroll
    for (int k = 0; k < 8; k++) {
        wmma::fragment<wmma::matrix_a, 16, 16, 16, __nv_bfloat16, wmma::row_major> ah0, ah1, al0, al1;
        wmma::load_matrix_sync(ah0, Ah + (row_m +  0) * LDA + k * 16, LDA);
        wmma::load_matrix_sync(ah1, Ah + (row_m + 16) * LDA + k * 16, LDA);
        wmma::load_matrix_sync(al0, Al + (row_m +  0) * LDA + k * 16, LDA);
        wmma::load_matrix_sync(al1, Al + (row_m + 16) * LDA + k * 16, LDA);
        #pragma unroll
        for (int ni = 0; ni < 4; ni++) {
            wmma::fragment<wmma::matrix_b, 16, 16, 16, __nv_bfloat16, wmma::row_major> bh, bl;
            wmma::load_matrix_sync(bh, GBh + (k * 16) * 128 + colb + ni * 16, 128);
            wmma::load_matrix_sync(bl, GBl + (k * 16) * 128 + colb + ni * 16, 128);
            wmma::mma_sync(acc[0][ni], ah0, bh, acc[0][ni]);
            wmma::mma_sync(acc[0][ni], ah0, bl, acc[0][ni]);
            wmma::mma_sync(acc[0][ni], al0, bh, acc[0][ni]);
            wmma::mma_sync(acc[1][ni], ah1, bh, acc[1][ni]);
            wmma::mma_sync(acc[1][ni], ah1, bl, acc[1][ni]);
            wmma::mma_sync(acc[1][ni], al1, bh, acc[1][ni]);
        }
    }
    __syncthreads();   // all bf16 stage reads done; F may alias

    #pragma unroll
    for (int mi = 0; mi < 2; mi++)
        #pragma unroll
        for (int ni = 0; ni < 4; ni++)
            wmma::store_matrix_sync(F + (row_m + mi * 16) * FLD + colb + ni * 16,
                                    acc[mi][ni], FLD, wmma::mem_row_major);
    __syncthreads();

    // epilogue: skip blend + per-type LN; warp w handles rows w*16..w*16+15
    float alpha = 1.f / (1.f + __expf(-skipv[s_t]));
    float beta = 1.f - alpha;
    int c0 = lane * 4;
    float4 bav = *(const float4*)(ba   + s_t * FDIM + c0);
    float4 gv  = *(const float4*)(ln_g + s_t * FDIM + c0);
    float4 bv2 = *(const float4*)(ln_b + s_t * FDIM + c0);
    int rbase = w * 16;
    for (int q = 0; q < 16; q++) {
        int m = rbase + q;
        int n = s_nl[m];
        if (n < 0) continue;
        float4 tr = *(float4*)(F + m * FLD + c0);
        float4 xv = *(const float4*)(x + (size_t)n * FDIM + c0);
        float4 v;
        v.x = (tr.x + bav.x) * alpha + xv.x * beta;
        v.y = (tr.y + bav.y) * alpha + xv.y * beta;
        v.z = (tr.z + bav.z) * alpha + xv.z * beta;
        v.w = (tr.w + bav.w) * alpha + xv.w * beta;
        float s  = v.x + v.y + v.z + v.w;
        float s2 = v.x*v.x + v.y*v.y + v.z*v.z + v.w*v.w;
        #pragma unroll
        for (int o = 16; o; o >>= 1) {
            s  += __shfl_xor_sync(0xFFFFFFFFu, s,  o);
            s2 += __shfl_xor_sync(0xFFFFFFFFu, s2, o);
        }
        float mu = s * (1.f / 128.f);
        float var = s2 * (1.f / 128.f) - mu * mu;
        float rstd = rsqrtf(var + 1e-5f);
        float4 ov;
        ov.x = (v.x - mu) * rstd * gv.x + bv2.x;
        ov.y = (v.y - mu) * rstd * gv.y + bv2.y;
        ov.z = (v.z - mu) * rstd * gv.z + bv2.z;
        ov.w = (v.w - mu) * rstd * gv.w + bv2.w;
        *(float4*)(out + (size_t)n * FDIM + c0) = ov;
    }
}

// ---------------- launch ----------------
extern "C" void kernel_launch(void* const* d_in, const int* in_sizes, int n_in,
                              void* d_out, int out_size) {
    const float* x       = (const float*)d_in[0];
    const int*   ntype   = (const int*)  d_in[1];
    const int*   src     = (const int*)  d_in[2];
    const int*   dst     = (const int*)  d_in[3];
    const int*   etype   = (const int*)  d_in[4];
    const float* Wk      = (const float*)d_in[5];
    const float* bk      = (const float*)d_in[6];
    const float* Wq      = (const float*)d_in[7];
    const float* bq      = (const float*)d_in[8];
    const float* Wv      = (const float*)d_in[9];
    const float* bv      = (const float*)d_in[10];
    const float* Wa      = (const float*)d_in[11];
    const float* ba      = (const float*)d_in[12];
    const float* rel_pri = (const float*)d_in[13];
    const float* rel_att = (const float*)d_in[14];
    const float* rel_msg = (const float*)d_in[15];
    const float* skipv   = (const float*)d_in[16];
    const float* ln_g    = (const float*)d_in[17];
    const float* ln_b    = (const float*)d_in[18];
    float* out = (float*)d_out;

    const int N = in_sizes[1];
    const int E = in_sizes[2];
    const int PROJ_SMEM = 128 * LDA * 2;               // 34816 B (Ah only)
    const int A_SMEM = 2 * 128 * LDA * 2;              // 69632 B (Ah|Al) for final
    const int F_SMEM = 128 * FLD * 4;                  // 67584 B
    const int FIN_SMEM = (A_SMEM > F_SMEM) ? A_SMEM : F_SMEM;

    cudaFuncSetAttribute(proj_wmma_kernel,  cudaFuncAttributeMaxDynamicSharedMemorySize, PROJ_SMEM);
    cudaFuncSetAttribute(final_wmma_kernel, cudaFuncAttributeMaxDynamicSharedMemorySize, FIN_SMEM);

    prep_kernel<<<1, 1024>>>(ntype, N);
    scatter_kernel<<<(N + 255) / 256, 256>>>(ntype, N);
    wconv_kernel<<<(TT * 4 * 128 * 32 + 255) / 256, 256>>>(Wk, Wq, Wv, Wa);
    proj_wmma_kernel<<<NL_CAP / 128, 256, PROJ_SMEM>>>(x, ntype, bk, bq, bv);   // profiled slot
    zero_kernel<<<4096, 256>>>();
    score_kernel<<<2048, 256>>>(src, dst, etype, rel_pri, rel_att, E);
    agg_kernel<<<2048, 256>>>(src, dst, etype, rel_msg, E);
    final_wmma_kernel<<<NL_CAP / 128, 256, FIN_SMEM>>>(x, ntype, ba, skipv, ln_g, ln_b, out);
}

// round 10
// speedup vs baseline: 1.5666x; 1.1939x over previous
#include <cuda_runtime.h>
#include <cuda_bf16.h>
#include <mma.h>
#include <stdint.h>
#include <math.h>

using namespace nvcuda;

// Problem constants (AttentionLayer_11776800325798)
#define NMAX   50000
#define EMAX   500000
#define TT     3
#define RR     5
#define HH     8
#define DKK    16
#define FDIM   128
#define NRH    (NMAX * RR * HH)                      // 2,000,000
#define NL_CAP (((NMAX / 128) + TT + 1) * 128)       // 50432, 128-padded per type
#define SQRT_DK 4.0f
#define LDA 136                                      // bf16 elems per row (128 + 8 pad)
#define FLD 132                                      // fp32 staging tile stride

// ---------------- scratch (static __device__, no allocation) ----------------
__device__ __nv_bfloat16 g_kb[NMAX * FDIM];
__device__ __nv_bfloat16 g_qb[NMAX * FDIM];
__device__ __nv_bfloat16 g_vb[NMAX * FDIM];
__device__ __nv_bfloat16 g_kt[(size_t)NMAX * RR * FDIM];   // k~ = k @ bd(rel_att[r]), 64MB
__device__ __nv_bfloat16 g_vt[(size_t)NMAX * RR * FDIM];   // v~ = v @ bd(rel_msg[r]), 64MB
__device__ float    g_acc[NMAX * FDIM];
__device__ float    g_a[EMAX * HH];
__device__ float    g_den[NRH];
__device__ int      g_nlist[NL_CAP];
__device__ int      g_cur[TT];
__device__ int      g_poff[TT + 1];
// pre-converted weights: [type][set(k,q,v,a)][hi|lo] each 128x128 bf16 row-major (32KB)
__device__ __align__(16) unsigned char g_wB[TT * 4 * 2 * 32768];
// bf16 relation blocks [r][h][16][16]
__device__ __align__(16) __nv_bfloat16 g_relab[RR * HH * 256];
__device__ __align__(16) __nv_bfloat16 g_relmb[RR * HH * 256];

// fp32 -> bf16 hi + bf16 lo (packed pairs)
__device__ __forceinline__ uint32_t bfsplit(float a, float b, uint32_t& lo) {
    __nv_bfloat162 h = __floats2bfloat162_rn(a, b);
    float ra = a - __bfloat162float(h.x);
    float rb = b - __bfloat162float(h.y);
    __nv_bfloat162 l = __floats2bfloat162_rn(ra, rb);
    lo = *reinterpret_cast<uint32_t*>(&l);
    return *reinterpret_cast<uint32_t*>(&h);
}
__device__ __forceinline__ float2 bf2f2(uint32_t u) {
    __nv_bfloat162 b = *reinterpret_cast<__nv_bfloat162*>(&u);
    return __bfloat1622float2(b);
}
__device__ __forceinline__ uint32_t f2bf2(float a, float b) {
    __nv_bfloat162 p = __floats2bfloat162_rn(a, b);
    return *reinterpret_cast<uint32_t*>(&p);
}

// ============================================================================
// K1: prep — fused counter zero + type histogram + scan + nlist init (1 block)
// ============================================================================
__global__ __launch_bounds__(1024) void prep_kernel(const int* __restrict__ ntype, int N) {
    __shared__ int scnt[TT];
    int tid = threadIdx.x;
    if (tid < TT) scnt[tid] = 0;
    __syncthreads();
    int c0 = 0, c1 = 0, c2 = 0;
    for (int i = tid; i < N; i += 1024) {
        int t = ntype[i];
        c0 += (t == 0); c1 += (t == 1); c2 += (t == 2);
    }
    if (c0) atomicAdd(&scnt[0], c0);
    if (c1) atomicAdd(&scnt[1], c1);
    if (c2) atomicAdd(&scnt[2], c2);
    __syncthreads();
    if (tid == 0) {
        int o = 0;
        for (int t = 0; t < TT; t++) { g_poff[t] = o; o += ((scnt[t] + 127) / 128) * 128; }
        g_poff[TT] = o;
    }
    if (tid < TT) g_cur[tid] = 0;
    for (int i = tid; i < NL_CAP; i += 1024) g_nlist[i] = -1;
}

// ============================================================================
// K2: scatter nodes into type-sorted, 128-padded list (warp-aggregated)
// ============================================================================
__global__ void scatter_kernel(const int* __restrict__ ntype, int N) {
    int i = blockIdx.x * blockDim.x + threadIdx.x;
    int t = (i < N) ? ntype[i] : -1;
    #pragma unroll
    for (int tt = 0; tt < TT; tt++) {
        unsigned mask = __ballot_sync(0xFFFFFFFFu, t == tt);
        if (t == tt) {
            int lane = threadIdx.x & 31;
            int leader = __ffs(mask) - 1;
            int rank = __popc(mask & ((1u << lane) - 1));
            int base = 0;
            if (lane == leader) base = atomicAdd(&g_cur[tt], __popc(mask));
            base = __shfl_sync(mask, base, leader);
            g_nlist[g_poff[tt] + base + rank] = i;
        }
    }
}

// ============================================================================
// K3: weight pre-conversion: all 4 W sets -> bf16 hi/lo row-major [128][128]
// ============================================================================
__global__ void wconv_kernel(const float* __restrict__ Wk, const float* __restrict__ Wq,
                             const float* __restrict__ Wv, const float* __restrict__ Wa) {
    int idx = blockIdx.x * blockDim.x + threadIdx.x;
    if (idx >= TT * 4 * 128 * 32) return;
    int c = (idx & 31) * 4;
    int kk = (idx >> 5) & 127;
    int g = idx >> 12;                             // 0..11 = t*4+set
    int set = g & 3, t = g >> 2;
    const float* W = ((set == 0) ? Wk : (set == 1) ? Wq : (set == 2) ? Wv : Wa) + t * FDIM * FDIM;
    float4 f = *(const float4*)(W + kk * FDIM + c);
    uint32_t l0, l1;
    uint32_t h0 = bfsplit(f.x, f.y, l0), h1 = bfsplit(f.z, f.w, l1);
    __nv_bfloat16* hi = (__nv_bfloat16*)(g_wB + (size_t)g * 65536);
    __nv_bfloat16* lo = hi + 128 * 128;
    *(uint32_t*)(hi + kk * 128 + c)     = h0;
    *(uint32_t*)(hi + kk * 128 + c + 2) = h1;
    *(uint32_t*)(lo + kk * 128 + c)     = l0;
    *(uint32_t*)(lo + kk * 128 + c + 2) = l1;
}

// ============================================================================
// K4: typed projections via wmma plain bf16.             [PROFILED SLOT #4]
// ============================================================================
__global__ __launch_bounds__(256, 2) void proj_wmma_kernel(
    const float* __restrict__ x, const int* __restrict__ ntype,
    const float* __restrict__ bk, const float* __restrict__ bq,
    const float* __restrict__ bv)
{
    extern __shared__ __align__(16) char dynsm[];
    __nv_bfloat16* Ah = (__nv_bfloat16*)dynsm;
    __shared__ int s_nl[128];
    __shared__ int s_t;
    __shared__ __align__(16) float stg[8][16][24];

    int tid = threadIdx.x, w = tid >> 5, lane = tid & 31;
    if (tid < 128) s_nl[tid] = g_nlist[blockIdx.x * 128 + tid];
    __syncthreads();
    if (tid == 0) {
        int t = -1;
        for (int m = 0; m < 128; m++) if (s_nl[m] >= 0) { t = ntype[s_nl[m]]; break; }
        s_t = t;
    }
    __syncthreads();
    if (s_t < 0) return;

    for (int idx = tid; idx < 128 * 32; idx += 256) {
        int m = idx >> 5, c = (idx & 31) * 4;
        int n = s_nl[m];
        float4 f = (n >= 0) ? *(const float4*)(x + (size_t)n * FDIM + c)
                            : make_float4(0.f, 0.f, 0.f, 0.f);
        *(uint32_t*)(Ah + m * LDA + c)     = f2bf2(f.x, f.y);
        *(uint32_t*)(Ah + m * LDA + c + 2) = f2bf2(f.z, f.w);
    }
    __syncthreads();

    int rg = w & 3, cg = w >> 2;
    int row_m = rg * 32;
    int colb = cg * 64;
    int r = lane >> 1, c0 = (lane & 1) * 8;

    for (int set = 0; set < 3; set++) {
        const __nv_bfloat16* GBh = (const __nv_bfloat16*)(g_wB + (size_t)(s_t * 4 + set) * 65536);

        wmma::fragment<wmma::accumulator, 16, 16, 16, float> acc[2][4];
        #pragma unroll
        for (int mi = 0; mi < 2; mi++)
            #pragma unroll
            for (int ni = 0; ni < 4; ni++) wmma::fill_fragment(acc[mi][ni], 0.f);

        #pragma unroll
        for (int k = 0; k < 8; k++) {
            wmma::fragment<wmma::matrix_a, 16, 16, 16, __nv_bfloat16, wmma::row_major> ah0, ah1;
            wmma::load_matrix_sync(ah0, Ah + (row_m +  0) * LDA + k * 16, LDA);
            wmma::load_matrix_sync(ah1, Ah + (row_m + 16) * LDA + k * 16, LDA);
            #pragma unroll
            for (int ni = 0; ni < 4; ni++) {
                wmma::fragment<wmma::matrix_b, 16, 16, 16, __nv_bfloat16, wmma::row_major> bh;
                wmma::load_matrix_sync(bh, GBh + (k * 16) * 128 + colb + ni * 16, 128);
                wmma::mma_sync(acc[0][ni], ah0, bh, acc[0][ni]);
                wmma::mma_sync(acc[1][ni], ah1, bh, acc[1][ni]);
            }
        }

        __nv_bfloat16* ob = (set == 0) ? g_kb : (set == 1) ? g_qb : g_vb;
        const float* bias = ((set == 0) ? bk : (set == 1) ? bq : bv) + s_t * FDIM;
        #pragma unroll
        for (int mi = 0; mi < 2; mi++) {
            int gr = s_nl[row_m + mi * 16 + r];
            #pragma unroll
            for (int ni = 0; ni < 4; ni++) {
                wmma::store_matrix_sync(&stg[w][0][0], acc[mi][ni], 24, wmma::mem_row_major);
                __syncwarp();
                if (gr >= 0) {
                    int col = colb + ni * 16 + c0;
                    float4 v0 = *(float4*)&stg[w][r][c0];
                    float4 v1 = *(float4*)&stg[w][r][c0 + 4];
                    v0.x += bias[col + 0]; v0.y += bias[col + 1];
                    v0.z += bias[col + 2]; v0.w += bias[col + 3];
                    v1.x += bias[col + 4]; v1.y += bias[col + 5];
                    v1.z += bias[col + 6]; v1.w += bias[col + 7];
                    uint4 pk = make_uint4(f2bf2(v0.x, v0.y), f2bf2(v0.z, v0.w),
                                          f2bf2(v1.x, v1.y), f2bf2(v1.z, v1.w));
                    *(uint4*)(ob + (size_t)gr * FDIM + col) = pk;
                }
                __syncwarp();
            }
        }
    }
}

// ============================================================================
// K5: relation matrices -> bf16 tables
// ============================================================================
__global__ void relconv_kernel(const float* __restrict__ rel_att,
                               const float* __restrict__ rel_msg) {
    int i = blockIdx.x * blockDim.x + threadIdx.x;
    if (i >= RR * HH * 128) return;
    float2 fa = *(const float2*)(rel_att + i * 2);
    float2 fm = *(const float2*)(rel_msg + i * 2);
    *(uint32_t*)(g_relab + i * 2) = f2bf2(fa.x, fa.y);
    *(uint32_t*)(g_relmb + i * 2) = f2bf2(fm.x, fm.y);
}

// ============================================================================
// K6: zero accumulators (g_acc, g_den)
// ============================================================================
__global__ void zero_kernel() {
    int stride = gridDim.x * blockDim.x;
    for (int idx = blockIdx.x * blockDim.x + threadIdx.x; idx < NMAX * FDIM; idx += stride) {
        g_acc[idx] = 0.f;
        if (idx < NRH) g_den[idx] = 0.f;
    }
}

// ============================================================================
// K7: k~/v~ tables via wmma. Warp = 16 nodes; regular, gather-free.
// k~[n,r,h,:] = k[n,h,:] @ rel_att[r,h];  v~ analogous with rel_msg.
// ============================================================================
__global__ __launch_bounds__(128) void ktvt_kernel() {
    extern __shared__ __align__(16) float stg2[];   // [4 warps][16*132]
    int w = threadIdx.x >> 5, lane = threadIdx.x & 31;
    int node0 = (blockIdx.x * 4 + w) * 16;
    if (node0 >= NMAX) return;
    float* S = stg2 + w * (16 * FLD);
    int row = lane >> 1, chalf = (lane & 1) * 64;

    for (int set = 0; set < 2; set++) {
        const __nv_bfloat16* srcb = (set == 0) ? g_kb : g_vb;
        const __nv_bfloat16* relb = (set == 0) ? g_relab : g_relmb;
        __nv_bfloat16* dstt = (set == 0) ? g_kt : g_vt;

        wmma::fragment<wmma::matrix_a, 16, 16, 16, __nv_bfloat16, wmma::row_major> a[8];
        #pragma unroll
        for (int h = 0; h < 8; h++)
            wmma::load_matrix_sync(a[h], srcb + (size_t)node0 * FDIM + h * 16, FDIM);

        for (int r = 0; r < RR; r++) {
            #pragma unroll
            for (int h = 0; h < 8; h++) {
                wmma::fragment<wmma::matrix_b, 16, 16, 16, __nv_bfloat16, wmma::row_major> b;
                wmma::load_matrix_sync(b, relb + (r * HH + h) * 256, 16);
                wmma::fragment<wmma::accumulator, 16, 16, 16, float> acc;
                wmma::fill_fragment(acc, 0.f);
                wmma::mma_sync(acc, a[h], b, acc);
                wmma::store_matrix_sync(S + h * 16, acc, FLD, wmma::mem_row_major);
            }
            __syncwarp();
            const float* Sr = S + row * FLD + chalf;
            __nv_bfloat16* drow = dstt + ((size_t)(node0 + row) * RR + r) * FDIM + chalf;
            #pragma unroll
            for (int u = 0; u < 8; u++) {
                float4 f0 = *(const float4*)(Sr + u * 8);
                float4 f1 = *(const float4*)(Sr + u * 8 + 4);
                *(uint4*)(drow + u * 8) = make_uint4(f2bf2(f0.x, f0.y), f2bf2(f0.z, f0.w),
                                                     f2bf2(f1.x, f1.y), f2bf2(f1.z, f1.w));
            }
            __syncwarp();
        }
    }
}

// ============================================================================
// K8: edge scores = dot(k~[s,r], q[d]) per head + exp + segment denom.
// Warp per edge; lane = h*4 + qq. Pure L2-gather kernel.
// ============================================================================
__global__ __launch_bounds__(256) void score2_kernel(
    const int* __restrict__ src, const int* __restrict__ dst,
    const int* __restrict__ etype, const float* __restrict__ rel_pri, int E) {
    __shared__ float s_pri[RR * HH];
    if (threadIdx.x < RR * HH) s_pri[threadIdx.x] = rel_pri[threadIdx.x] * (1.0f / SQRT_DK);
    __syncthreads();

    int warp = threadIdx.x >> 5;
    int lane = threadIdx.x & 31;
    int h = lane >> 2, qq = lane & 3;
    int off = h * DKK + qq * 4;
    for (int e = blockIdx.x * 8 + warp; e < E; e += gridDim.x * 8) {
        int s = src[e], d = dst[e], r = etype[e];
        uint2 ku = *(const uint2*)(g_kt + ((size_t)s * RR + r) * FDIM + off);
        uint2 qu = *(const uint2*)(g_qb + (size_t)d * FDIM + off);
        float2 k0 = bf2f2(ku.x), k1 = bf2f2(ku.y);
        float2 q0 = bf2f2(qu.x), q1 = bf2f2(qu.y);
        float sc = k0.x * q0.x + k0.y * q0.y + k1.x * q1.x + k1.y * q1.y;
        sc += __shfl_xor_sync(0xFFFFFFFFu, sc, 1);
        sc += __shfl_xor_sync(0xFFFFFFFFu, sc, 2);
        sc *= s_pri[r * HH + h];
        if (qq == 0) {
            float p = __expf(sc);
            g_a[e * HH + h] = p;
            atomicAdd(&g_den[(d * RR + r) * HH + h], p);
        }
    }
}

// ============================================================================
// K9: aggregation = attw * v~[s,r] atomically into g_acc[d].
// ============================================================================
__global__ __launch_bounds__(256) void agg2_kernel(
    const int* __restrict__ src, const int* __restrict__ dst,
    const int* __restrict__ etype, int E) {
    int warp = threadIdx.x >> 5;
    int lane = threadIdx.x & 31;
    int h = lane >> 2, qq = lane & 3;
    int off = h * DKK + qq * 4;
    for (int e = blockIdx.x * 8 + warp; e < E; e += gridDim.x * 8) {
        int s = src[e], d = dst[e], r = etype[e];
        float p = g_a[e * HH + h];
        float den = g_den[(d * RR + r) * HH + h];
        float attw = p / den;
        uint2 vu = *(const uint2*)(g_vt + ((size_t)s * RR + r) * FDIM + off);
        float2 v0 = bf2f2(vu.x), v1 = bf2f2(vu.y);
        float4 add = make_float4(attw * v0.x, attw * v0.y, attw * v1.x, attw * v1.y);
        atomicAdd((float4*)(g_acc + (size_t)d * FDIM + off), add);
    }
}

// ============================================================================
// K10: mean-over-etypes, Wa proj (wmma split-bf16), skip blend, per-type LN
// ============================================================================
__global__ __launch_bounds__(256) void final_wmma_kernel(
    const float* __restrict__ x, const int* __restrict__ ntype,
    const float* __restrict__ ba, const float* __restrict__ skipv,
    const float* __restrict__ ln_g, const float* __restrict__ ln_b,
    float* __restrict__ out)
{
    extern __shared__ __align__(16) char dynsm[];
    __nv_bfloat16* Ah = (__nv_bfloat16*)dynsm;
    __nv_bfloat16* Al = Ah + 128 * LDA;
    float* F = (float*)dynsm;                 // fp32 tile [128][FLD]; aliased AFTER GEMM
    __shared__ int s_nl[128];
    __shared__ int s_t;
    __shared__ float s_scp[128];

    int tid = threadIdx.x, w = tid >> 5, lane = tid & 31;
    if (tid < 128) s_nl[tid] = g_nlist[blockIdx.x * 128 + tid];
    __syncthreads();
    if (tid == 0) {
        int t = -1;
        for (int m = 0; m < 128; m++) if (s_nl[m] >= 0) { t = ntype[s_nl[m]]; break; }
        s_t = t;
    }
    if (tid < 128) {
        int n = s_nl[tid];
        float inv = 1.f;
        if (n >= 0) {
            int cp = 0;
            for (int r = 0; r < RR; r++) cp += (g_den[(n * RR + r) * HH] > 0.f) ? 1 : 0;
            if (cp < 1) cp = 1;
            inv = 1.f / (float)cp;
        }
        s_scp[tid] = inv;
    }
    __syncthreads();
    if (s_t < 0) return;

    for (int idx = tid; idx < 128 * 32; idx += 256) {
        int m = idx >> 5, c = (idx & 31) * 4;
        int n = s_nl[m];
        float4 f = make_float4(0.f, 0.f, 0.f, 0.f);
        if (n >= 0) {
            f = *(const float4*)(g_acc + (size_t)n * FDIM + c);
            float sc = s_scp[m];
            f.x *= sc; f.y *= sc; f.z *= sc; f.w *= sc;
        }
        uint32_t l0, l1;
        uint32_t h0 = bfsplit(f.x, f.y, l0), h1 = bfsplit(f.z, f.w, l1);
        *(uint32_t*)(Ah + m * LDA + c)     = h0;
        *(uint32_t*)(Ah + m * LDA + c + 2) = h1;
        *(uint32_t*)(Al + m * LDA + c)     = l0;
        *(uint32_t*)(Al + m * LDA + c + 2) = l1;
    }
    __syncthreads();

    int rg = w & 3, cg = w >> 2;
    int row_m = rg * 32;
    int colb = cg * 64;
    const __nv_bfloat16* GBh = (const __nv_bfloat16*)(g_wB + (size_t)(s_t * 4 + 3) * 65536);
    const __nv_bfloat16* GBl = GBh + 128 * 128;

    wmma::fragment<wmma::accumulator, 16, 16, 16, float> acc[2][4];
    #pragma unroll
    for (int mi = 0; mi < 2; mi++)
        #pragma unroll
        for (int ni = 0; ni < 4; ni++) wmma::fill_fragment(acc[mi][ni], 0.f);

    #pragma unroll
    for (int k = 0; k < 8; k++) {
        wmma::fragment<wmma::matrix_a, 16, 16, 16, __nv_bfloat16, wmma::row_major> ah0, ah1, al0, al1;
        wmma::load_matrix_sync(ah0, Ah + (row_m +  0) * LDA + k * 16, LDA);
        wmma::load_matrix_sync(ah1, Ah + (row_m + 16) * LDA + k * 16, LDA);
        wmma::load_matrix_sync(al0, Al + (row_m +  0) * LDA + k * 16, LDA);
        wmma::load_matrix_sync(al1, Al + (row_m + 16) * LDA + k * 16, LDA);
        #pragma unroll
        for (int ni = 0; ni < 4; ni++) {
            wmma::fragment<wmma::matrix_b, 16, 16, 16, __nv_bfloat16, wmma::row_major> bh, bl;
            wmma::load_matrix_sync(bh, GBh + (k * 16) * 128 + colb + ni * 16, 128);
            wmma::load_matrix_sync(bl, GBl + (k * 16) * 128 + colb + ni * 16, 128);
            wmma::mma_sync(acc[0][ni], ah0, bh, acc[0][ni]);
            wmma::mma_sync(acc[0][ni], ah0, bl, acc[0][ni]);
            wmma::mma_sync(acc[0][ni], al0, bh, acc[0][ni]);
            wmma::mma_sync(acc[1][ni], ah1, bh, acc[1][ni]);
            wmma::mma_sync(acc[1][ni], ah1, bl, acc[1][ni]);
            wmma::mma_sync(acc[1][ni], al1, bh, acc[1][ni]);
        }
    }
    __syncthreads();

    #pragma unroll
    for (int mi = 0; mi < 2; mi++)
        #pragma unroll
        for (int ni = 0; ni < 4; ni++)
            wmma::store_matrix_sync(F + (row_m + mi * 16) * FLD + colb + ni * 16,
                                    acc[mi][ni], FLD, wmma::mem_row_major);
    __syncthreads();

    float alpha = 1.f / (1.f + __expf(-skipv[s_t]));
    float beta = 1.f - alpha;
    int c0 = lane * 4;
    float4 bav = *(const float4*)(ba   + s_t * FDIM + c0);
    float4 gv  = *(const float4*)(ln_g + s_t * FDIM + c0);
    float4 bv2 = *(const float4*)(ln_b + s_t * FDIM + c0);
    int rbase = w * 16;
    for (int q = 0; q < 16; q++) {
        int m = rbase + q;
        int n = s_nl[m];
        if (n < 0) continue;
        float4 tr = *(float4*)(F + m * FLD + c0);
        float4 xv = *(const float4*)(x + (size_t)n * FDIM + c0);
        float4 v;
        v.x = (tr.x + bav.x) * alpha + xv.x * beta;
        v.y = (tr.y + bav.y) * alpha + xv.y * beta;
        v.z = (tr.z + bav.z) * alpha + xv.z * beta;
        v.w = (tr.w + bav.w) * alpha + xv.w * beta;
        float s  = v.x + v.y + v.z + v.w;
        float s2 = v.x*v.x + v.y*v.y + v.z*v.z + v.w*v.w;
        #pragma unroll
        for (int o = 16; o; o >>= 1) {
            s  += __shfl_xor_sync(0xFFFFFFFFu, s,  o);
            s2 += __shfl_xor_sync(0xFFFFFFFFu, s2, o);
        }
        float mu = s * (1.f / 128.f);
        float var = s2 * (1.f / 128.f) - mu * mu;
        float rstd = rsqrtf(var + 1e-5f);
        float4 ov;
        ov.x = (v.x - mu) * rstd * gv.x + bv2.x;
        ov.y = (v.y - mu) * rstd * gv.y + bv2.y;
        ov.z = (v.z - mu) * rstd * gv.z + bv2.z;
        ov.w = (v.w - mu) * rstd * gv.w + bv2.w;
        *(float4*)(out + (size_t)n * FDIM + c0) = ov;
    }
}

// ---------------- launch ----------------
extern "C" void kernel_launch(void* const* d_in, const int* in_sizes, int n_in,
                              void* d_out, int out_size) {
    const float* x       = (const float*)d_in[0];
    const int*   ntype   = (const int*)  d_in[1];
    const int*   src     = (const int*)  d_in[2];
    const int*   dst     = (const int*)  d_in[3];
    const int*   etype   = (const int*)  d_in[4];
    const float* Wk      = (const float*)d_in[5];
    const float* bk      = (const float*)d_in[6];
    const float* Wq      = (const float*)d_in[7];
    const float* bq      = (const float*)d_in[8];
    const float* Wv      = (const float*)d_in[9];
    const float* bv      = (const float*)d_in[10];
    const float* Wa      = (const float*)d_in[11];
    const float* ba      = (const float*)d_in[12];
    const float* rel_pri = (const float*)d_in[13];
    const float* rel_att = (const float*)d_in[14];
    const float* rel_msg = (const float*)d_in[15];
    const float* skipv   = (const float*)d_in[16];
    const float* ln_g    = (const float*)d_in[17];
    const float* ln_b    = (const float*)d_in[18];
    float* out = (float*)d_out;

    const int N = in_sizes[1];
    const int E = in_sizes[2];
    const int PROJ_SMEM = 128 * LDA * 2;               // 34816 B
    const int A_SMEM = 2 * 128 * LDA * 2;              // 69632 B
    const int F_SMEM = 128 * FLD * 4;                  // 67584 B
    const int FIN_SMEM = (A_SMEM > F_SMEM) ? A_SMEM : F_SMEM;
    const int KTVT_SMEM = 4 * 16 * FLD * 4;            // 33792 B

    cudaFuncSetAttribute(proj_wmma_kernel,  cudaFuncAttributeMaxDynamicSharedMemorySize, PROJ_SMEM);
    cudaFuncSetAttribute(final_wmma_kernel, cudaFuncAttributeMaxDynamicSharedMemorySize, FIN_SMEM);
    cudaFuncSetAttribute(ktvt_kernel,       cudaFuncAttributeMaxDynamicSharedMemorySize, KTVT_SMEM);

    prep_kernel<<<1, 1024>>>(ntype, N);
    scatter_kernel<<<(N + 255) / 256, 256>>>(ntype, N);
    wconv_kernel<<<(TT * 4 * 128 * 32 + 255) / 256, 256>>>(Wk, Wq, Wv, Wa);
    proj_wmma_kernel<<<NL_CAP / 128, 256, PROJ_SMEM>>>(x, ntype, bk, bq, bv);   // profiled
    relconv_kernel<<<(RR * HH * 128 + 255) / 256, 256>>>(rel_att, rel_msg);
    zero_kernel<<<4096, 256>>>();
    ktvt_kernel<<<(NMAX / 16 + 3) / 4, 128, KTVT_SMEM>>>();
    score2_kernel<<<2048, 256>>>(src, dst, etype, rel_pri, E);
    agg2_kernel<<<2048, 256>>>(src, dst, etype, E);
    final_wmma_kernel<<<NL_CAP / 128, 256, FIN_SMEM>>>(x, ntype, ba, skipv, ln_g, ln_b, out);
}